// round 1
// baseline (speedup 1.0000x reference)
#include <cuda_runtime.h>

#define NN 32     // graph nodes
#define C1 60     // input channels
#define H  128    // hidden channels
#define KK 5      // chebyshev order

// ---- device-global scratch (allocation-free rule) ----
__device__ float g_A[4][NN][NN];     // A1=I, A2=L, A3=2L^2-I, A4=2L*A3-A2
__device__ float g_W1[C1][4 * H];    // repacked: [c][k*128+o] = w1[(c*5+k+1)*128+o]
__device__ float g_W2[H][4 * H];     // repacked: [c][k*128+o] = w2[(c*5+k+1)*128+o]
__device__ float g_B1[H];            // b1 + sum_c w1[c*5+0]
__device__ float g_B2[H];            // b2 + sum_c w2[c*5+0]

// ------------------------------------------------------------------
// Precompute: Laplacian polynomials + weight repack + bias folding
// one block, 1024 threads (n = tid/32, m = tid%32)
// ------------------------------------------------------------------
__global__ void precompute_kernel(const float* __restrict__ adj,
                                  const float* __restrict__ adj_bias,
                                  const float* __restrict__ w1,
                                  const float* __restrict__ b1,
                                  const float* __restrict__ w2,
                                  const float* __restrict__ b2) {
    __shared__ float a[NN][NN];
    __shared__ float L[NN][NN];
    __shared__ float A3[NN][NN];
    __shared__ float dre[NN];

    int tid = threadIdx.x;
    int n = tid >> 5, m = tid & 31;

    float bias = adj_bias[0];
    a[n][m] = fmaxf(adj[n * NN + m] + bias, 0.0f);
    __syncthreads();

    if (m == 0) {
        float s = 0.0f;
        for (int j = 0; j < NN; j++) s += a[n][j];
        dre[n] = 1.0f / sqrtf(s + 1e-5f);
    }
    __syncthreads();

    L[n][m] = (n == m ? 1.0f : 0.0f) - dre[n] * a[n][m] * dre[m];
    __syncthreads();

    float s = 0.0f;
    for (int j = 0; j < NN; j++) s += L[n][j] * L[j][m];
    A3[n][m] = 2.0f * s - (n == m ? 1.0f : 0.0f);
    __syncthreads();

    float s2 = 0.0f;
    for (int j = 0; j < NN; j++) s2 += L[n][j] * A3[j][m];
    float a4 = 2.0f * s2 - L[n][m];

    g_A[0][n][m] = (n == m ? 1.0f : 0.0f);
    g_A[1][n][m] = L[n][m];
    g_A[2][n][m] = A3[n][m];
    g_A[3][n][m] = a4;

    // repack W1: column (k,o), k=0..3 maps to chebyshev term k+1
    for (int idx = tid; idx < C1 * 4 * H; idx += blockDim.x) {
        int c = idx / (4 * H);
        int col = idx % (4 * H);
        int k = col >> 7, o = col & (H - 1);
        g_W1[c][col] = w1[(c * KK + k + 1) * H + o];
    }
    // repack W2
    for (int idx = tid; idx < H * 4 * H; idx += blockDim.x) {
        int c = idx / (4 * H);
        int col = idx % (4 * H);
        int k = col >> 7, o = col & (H - 1);
        g_W2[c][col] = w2[(c * KK + k + 1) * H + o];
    }
    // folded biases (T0 = ones -> sum of k=0 weight rows)
    if (tid < H) {
        float s1 = b1[tid];
        for (int c = 0; c < C1; c++) s1 += w1[(c * KK) * H + tid];
        g_B1[tid] = s1;
        float sb = b2[tid];
        for (int c = 0; c < H; c++) sb += w2[(c * KK) * H + tid];
        g_B2[tid] = sb;
    }
}

// ------------------------------------------------------------------
// Fused DGCNN forward: one block (128 threads) per batch element.
// Thread t owns output channel o=t for both layers; Z columns and
// A-apply accumulate in registers. Only h1 round-trips through smem.
// ------------------------------------------------------------------
__global__ __launch_bounds__(128) void dgcnn_kernel(
    const float* __restrict__ x,
    const float* __restrict__ fc_w,
    const float* __restrict__ fc_b,
    float* __restrict__ out) {

    __shared__ float xs[NN][C1];        // 7.5 KB
    __shared__ float As[4][NN][NN];     // 16 KB
    __shared__ float h1s[NN][H];        // 16 KB
    __shared__ float red[2][128];

    const int t = threadIdx.x;
    const int b = blockIdx.x;

    // load x_b and A matrices
    const float* xb = x + (size_t)b * NN * C1;
    for (int i = t; i < NN * C1; i += 128) ((float*)xs)[i] = xb[i];
    for (int i = t; i < 4 * NN * NN; i += 128)
        ((float*)As)[i] = ((const float*)g_A)[i];
    __syncthreads();

    float acch[NN];
    {
        float bb = g_B1[t];
#pragma unroll
        for (int n = 0; n < NN; n++) acch[n] = bb;
    }

    // ---------- layer 1 ----------
    for (int k = 0; k < 4; k++) {
        float accm[NN];
#pragma unroll
        for (int m = 0; m < NN; m++) accm[m] = 0.0f;

        // Z_k column t: [32] = xs[32,60] @ W1[:, k*128+t]
        for (int c4 = 0; c4 < C1 / 4; c4++) {
            const float w0 = g_W1[4 * c4 + 0][k * H + t];
            const float w1v = g_W1[4 * c4 + 1][k * H + t];
            const float w2v = g_W1[4 * c4 + 2][k * H + t];
            const float w3v = g_W1[4 * c4 + 3][k * H + t];
#pragma unroll
            for (int m = 0; m < NN; m++) {
                float4 xv = *(const float4*)&xs[m][4 * c4];
                accm[m] += xv.x * w0 + xv.y * w1v + xv.z * w2v + xv.w * w3v;
            }
        }
        // h1[:,t] += A_k @ Z_k[:,t]
#pragma unroll
        for (int n = 0; n < NN; n++) {
            float s = 0.0f;
#pragma unroll
            for (int m4 = 0; m4 < NN / 4; m4++) {
                float4 a4 = *(const float4*)&As[k][n][4 * m4];
                s += a4.x * accm[4 * m4 + 0] + a4.y * accm[4 * m4 + 1] +
                     a4.z * accm[4 * m4 + 2] + a4.w * accm[4 * m4 + 3];
            }
            acch[n] += s;
        }
    }

    // relu -> h1 in smem
#pragma unroll
    for (int n = 0; n < NN; n++) h1s[n][t] = fmaxf(acch[n], 0.0f);
    __syncthreads();

    // ---------- layer 2 ----------
    {
        float bb = g_B2[t];
#pragma unroll
        for (int n = 0; n < NN; n++) acch[n] = bb;
    }
    for (int k = 0; k < 4; k++) {
        float accm[NN];
#pragma unroll
        for (int m = 0; m < NN; m++) accm[m] = 0.0f;

        for (int c4 = 0; c4 < H / 4; c4++) {
            const float w0 = g_W2[4 * c4 + 0][k * H + t];
            const float w1v = g_W2[4 * c4 + 1][k * H + t];
            const float w2v = g_W2[4 * c4 + 2][k * H + t];
            const float w3v = g_W2[4 * c4 + 3][k * H + t];
#pragma unroll
            for (int m = 0; m < NN; m++) {
                float4 hv = *(const float4*)&h1s[m][4 * c4];
                accm[m] += hv.x * w0 + hv.y * w1v + hv.z * w2v + hv.w * w3v;
            }
        }
#pragma unroll
        for (int n = 0; n < NN; n++) {
            float s = 0.0f;
#pragma unroll
            for (int m4 = 0; m4 < NN / 4; m4++) {
                float4 a4 = *(const float4*)&As[k][n][4 * m4];
                s += a4.x * accm[4 * m4 + 0] + a4.y * accm[4 * m4 + 1] +
                     a4.z * accm[4 * m4 + 2] + a4.w * accm[4 * m4 + 3];
            }
            acch[n] += s;
        }
    }

    // ---------- relu + FC (h2 column stays in regs) ----------
    float p0 = 0.0f, p1 = 0.0f;
#pragma unroll
    for (int n = 0; n < NN; n++) {
        float h = fmaxf(acch[n], 0.0f);
        p0 += h * fc_w[n * H + t];
        p1 += h * fc_w[NN * H + n * H + t];
    }
    red[0][t] = p0;
    red[1][t] = p1;
    __syncthreads();
    for (int s = 64; s > 0; s >>= 1) {
        if (t < s) {
            red[0][t] += red[0][t + s];
            red[1][t] += red[1][t + s];
        }
        __syncthreads();
    }
    if (t == 0) {
        out[b * 2 + 0] = red[0][0] + fc_b[0];
        out[b * 2 + 1] = red[1][0] + fc_b[1];
    }
}

// ------------------------------------------------------------------
extern "C" void kernel_launch(void* const* d_in, const int* in_sizes, int n_in,
                              void* d_out, int out_size) {
    const float* x        = (const float*)d_in[0];
    const float* adj      = (const float*)d_in[1];
    const float* adj_bias = (const float*)d_in[2];
    const float* w1       = (const float*)d_in[3];
    const float* b1       = (const float*)d_in[4];
    const float* w2       = (const float*)d_in[5];
    const float* b2       = (const float*)d_in[6];
    const float* fc_w     = (const float*)d_in[7];
    const float* fc_b     = (const float*)d_in[8];
    float* out = (float*)d_out;

    const int B = in_sizes[0] / (NN * C1);

    precompute_kernel<<<1, 1024>>>(adj, adj_bias, w1, b1, w2, b2);
    dgcnn_kernel<<<B, 128>>>(x, fc_w, fc_b, out);
}

// round 4
// speedup vs baseline: 1.6107x; 1.6107x over previous
#include <cuda_runtime.h>
#include <cuda_fp16.h>
#include <cstdint>

#define NNODE 32
#define CIN   60
#define HID   128
#define KCH   5

// ---- packed hi/lo fp16 constants (u32 = lo16:hi-part, hi16:lo-part) ----
__device__ uint32_t g_W1p[4][128][64];    // [k][o][c]  = w1[(c*5+k+1)*128+o]
__device__ uint32_t g_W2p[4][128][128];   // [k][o2][o] = w2[(o*5+k+1)*128+o2]
__device__ uint32_t g_Ap[4][32][32];      // A1=I, A2=L, A3=2L^2-I, A4=2L*A3-L
__device__ float    g_B1[128];
__device__ float    g_B2[128];

__device__ __forceinline__ uint32_t packhl(float v) {
    __half h = __float2half_rn(v);
    __half l = __float2half_rn(v - __half2float(h));
    return (uint32_t)__half_as_ushort(h) | ((uint32_t)__half_as_ushort(l) << 16);
}

// ------------------------------------------------------------------
__global__ void precompute_kernel(const float* __restrict__ adj,
                                  const float* __restrict__ adj_bias,
                                  const float* __restrict__ w1,
                                  const float* __restrict__ b1,
                                  const float* __restrict__ w2,
                                  const float* __restrict__ b2) {
    __shared__ float a[NNODE][NNODE];
    __shared__ float L[NNODE][NNODE];
    __shared__ float A3[NNODE][NNODE];
    __shared__ float dre[NNODE];

    int tid = threadIdx.x;
    int n = tid >> 5, m = tid & 31;

    float bias = adj_bias[0];
    a[n][m] = fmaxf(adj[n * NNODE + m] + bias, 0.0f);
    __syncthreads();
    if (m == 0) {
        float s = 0.0f;
        for (int j = 0; j < NNODE; j++) s += a[n][j];
        dre[n] = 1.0f / sqrtf(s + 1e-5f);
    }
    __syncthreads();
    L[n][m] = (n == m ? 1.0f : 0.0f) - dre[n] * a[n][m] * dre[m];
    __syncthreads();
    float s = 0.0f;
    for (int j = 0; j < NNODE; j++) s += L[n][j] * L[j][m];
    A3[n][m] = 2.0f * s - (n == m ? 1.0f : 0.0f);
    __syncthreads();
    float s2 = 0.0f;
    for (int j = 0; j < NNODE; j++) s2 += L[n][j] * A3[j][m];
    float a4 = 2.0f * s2 - L[n][m];

    // Abig pack (all 1024 threads cover 32x32)
    g_Ap[0][n][m] = packhl(n == m ? 1.0f : 0.0f);
    g_Ap[1][n][m] = packhl(L[n][m]);
    g_Ap[2][n][m] = packhl(A3[n][m]);
    g_Ap[3][n][m] = packhl(a4);

    // W1 pack [k][o][c], zero-pad c>=60
    for (int idx = tid; idx < 4 * 128 * 64; idx += blockDim.x) {
        int k = idx >> 13, r = idx & 8191;
        int o = r >> 6, c = r & 63;
        float v = (c < CIN) ? w1[(c * KCH + k + 1) * HID + o] : 0.0f;
        g_W1p[k][o][c] = packhl(v);
    }
    // W2 pack [k][o2][o]
    for (int idx = tid; idx < 4 * 128 * 128; idx += blockDim.x) {
        int k = idx >> 14, r = idx & 16383;
        int o2 = r >> 7, o = r & 127;
        g_W2p[k][o2][o] = packhl(w2[(o * KCH + k + 1) * HID + o2]);
    }
    // folded biases (T0 == ones)
    if (tid < HID) {
        float s1 = b1[tid];
        for (int c = 0; c < CIN; c++) s1 += w1[(c * KCH) * HID + tid];
        g_B1[tid] = s1;
        float sb = b2[tid];
        for (int c = 0; c < HID; c++) sb += w2[(c * KCH) * HID + tid];
        g_B2[tid] = sb;
    }
}

// ------------------------------------------------------------------
// mma helpers
// ------------------------------------------------------------------
__device__ __forceinline__ uint32_t smem_u32(const void* p) {
    uint32_t a;
    asm("{ .reg .u64 t; cvta.to.shared.u64 t, %1; cvt.u32.u64 %0, t; }"
        : "=r"(a) : "l"(p));
    return a;
}
__device__ __forceinline__ void ldsm4(uint32_t* r, uint32_t addr) {
    asm volatile("ldmatrix.sync.aligned.m8n8.x4.shared.b16 {%0,%1,%2,%3}, [%4];\n"
                 : "=r"(r[0]), "=r"(r[1]), "=r"(r[2]), "=r"(r[3]) : "r"(addr));
}
__device__ __forceinline__ void mma16816(float* d, const uint32_t* a,
                                         uint32_t b0, uint32_t b1) {
    asm volatile(
        "mma.sync.aligned.m16n8k16.row.col.f32.f16.f16.f32 "
        "{%0,%1,%2,%3},{%4,%5,%6,%7},{%8,%9},{%0,%1,%2,%3};\n"
        : "+f"(d[0]), "+f"(d[1]), "+f"(d[2]), "+f"(d[3])
        : "r"(a[0]), "r"(a[1]), "r"(a[2]), "r"(a[3]), "r"(b0), "r"(b1));
}

// ---- smem strides (halfs) ----
#define ST1 136   // X / W1 panels: [row][ hi 0..63 | lo 64..127 | pad ]
#define ST2 264   // H1 / W2 panels: [row][ hi 0..127 | lo 128..255 | pad ]
#define STZ 72    // Z: [o][ m-hi 0..31 | m-lo 32..63 | pad ]
#define STA 72    // Abig: same

// ---- smem regions (bytes) ----
#define OFF_R1 0        // layer1: Xs [128][ST1]  | layer2: H1 [128][ST2]
#define OFF_R2 67584    // layer1: W1 [128][ST1]  | layer2: W2 [128][ST2]
#define OFF_Z  135168   // per-warp 18432 B : [128][STZ]
#define OFF_A  208896   // [4][32][STA]
#define OFF_B1 227328
#define OFF_B2 227840
#define SMEM_TOTAL 228352

// channel-mix GEMM: D[32 x 128] = rows(a) x cols(b), 3 compensated passes.
// Output stored hi/lo transposed into zPtr[o][m].
template <int NCH, int SEG, int STRD>
__device__ __forceinline__ void gemm_cm(uint32_t aBase, uint32_t bBase,
                                        __half* zPtr, int lane) {
    const uint32_t lrow = (uint32_t)(lane & 15);
    const uint32_t lcol = (uint32_t)((lane >> 4) << 3);
    for (int hf = 0; hf < 4; hf++) {           // quarter of N=128 (4 col-tiles)
        float d[2][4][4];
#pragma unroll
        for (int rt = 0; rt < 2; rt++)
#pragma unroll
            for (int ct = 0; ct < 4; ct++)
#pragma unroll
                for (int e = 0; e < 4; e++) d[rt][ct][e] = 0.0f;

        for (int p = 0; p < 3; p++) {
            const int aoff = (p == 2) ? SEG : 0;
            const int boff = (p == 1) ? SEG : 0;
            for (int c = 0; c < NCH; c++) {
                const int ka = aoff + c * 16, kb = boff + c * 16;
                uint32_t A0[4], A1[4];
                ldsm4(A0, aBase + ((0 + lrow) * STRD + ka + lcol) * 2);
                ldsm4(A1, aBase + ((16 + lrow) * STRD + ka + lcol) * 2);
#pragma unroll
                for (int n2 = 0; n2 < 2; n2++) {
                    const int nt = hf * 4 + n2 * 2;   // of 16 n-tiles
                    uint32_t Bf[4];
                    ldsm4(Bf, bBase + ((nt * 8 + lrow) * STRD + kb + lcol) * 2);
                    mma16816(d[0][n2 * 2 + 0], A0, Bf[0], Bf[2]);
                    mma16816(d[0][n2 * 2 + 1], A0, Bf[1], Bf[3]);
                    mma16816(d[1][n2 * 2 + 0], A1, Bf[0], Bf[2]);
                    mma16816(d[1][n2 * 2 + 1], A1, Bf[1], Bf[3]);
                }
            }
        }
        // transpose-store hi/lo: Z[o][m]
#pragma unroll
        for (int rt = 0; rt < 2; rt++)
#pragma unroll
            for (int ct = 0; ct < 4; ct++)
#pragma unroll
                for (int e = 0; e < 4; e++) {
                    int m = rt * 16 + (lane >> 2) + ((e >> 1) << 3);
                    int o = (hf * 4 + ct) * 8 + ((lane & 3) << 1) + (e & 1);
                    float v = d[rt][ct][e];
                    __half hh = __float2half_rn(v);
                    zPtr[o * STZ + m] = hh;
                    zPtr[o * STZ + 32 + m] =
                        __float2half_rn(v - __half2float(hh));
                }
    }
}

// A-apply: acc[32n x 128o] += Abig_k (rows n, K=m) x Z (rows o, K=m)
__device__ __forceinline__ void apply_acc(float (&acc)[2][16][4],
                                          uint32_t aBase, uint32_t bBase,
                                          int lane) {
    const uint32_t lrow = (uint32_t)(lane & 15);
    const uint32_t lcol = (uint32_t)((lane >> 4) << 3);
    for (int p = 0; p < 3; p++) {
        const int aoff = (p == 2) ? 32 : 0;
        const int boff = (p == 1) ? 32 : 0;
        for (int c = 0; c < 2; c++) {
            const int ka = aoff + c * 16, kb = boff + c * 16;
            uint32_t A0[4], A1[4];
            ldsm4(A0, aBase + ((0 + lrow) * STA + ka + lcol) * 2);
            ldsm4(A1, aBase + ((16 + lrow) * STA + ka + lcol) * 2);
#pragma unroll
            for (int n2 = 0; n2 < 8; n2++) {
                uint32_t Bf[4];
                ldsm4(Bf, bBase + ((n2 * 16 + lrow) * STZ + kb + lcol) * 2);
                mma16816(acc[0][n2 * 2 + 0], A0, Bf[0], Bf[2]);
                mma16816(acc[0][n2 * 2 + 1], A0, Bf[1], Bf[3]);
                mma16816(acc[1][n2 * 2 + 0], A1, Bf[0], Bf[2]);
                mma16816(acc[1][n2 * 2 + 1], A1, Bf[1], Bf[3]);
            }
        }
    }
}

// ------------------------------------------------------------------
__global__ __launch_bounds__(128) void dgcnn_mma_kernel(
    const float* __restrict__ x,
    const float* __restrict__ fcw,
    const float* __restrict__ fcb,
    float* __restrict__ out) {

    extern __shared__ char smem[];
    __half* S = (__half*)smem;
    const uint32_t sb = smem_u32(smem);
    const int tid = threadIdx.x;
    const int w = tid >> 5, lane = tid & 31;

    float* sB1 = (float*)(smem + OFF_B1);
    float* sB2 = (float*)(smem + OFF_B2);
    __half* zPtr = (__half*)(smem + OFF_Z + w * 18432);
    const uint32_t zB = sb + OFF_Z + w * 18432;

    // ---- prologue ----
    // zero X region (incl pad columns)
    for (int i = tid; i < 128 * ST1 / 2; i += 128) ((uint32_t*)smem)[i] = 0;
    __syncthreads();
    {
        const float* xb = x + (size_t)blockIdx.x * 128 * CIN;
        for (int i = tid; i < 128 * CIN; i += 128) {
            int row = i / CIN, c = i - row * CIN;
            float v = xb[i];
            __half h = __float2half_rn(v);
            S[row * ST1 + c] = h;
            S[row * ST1 + 64 + c] = __float2half_rn(v - __half2float(h));
        }
        for (int i = tid; i < 4096; i += 128) {
            int k = i >> 10, n = (i >> 5) & 31, m = i & 31;
            uint32_t u = g_Ap[k][n][m];
            __half2 p = *(__half2*)&u;
            int base = OFF_A / 2 + (k * 32 + n) * STA;
            S[base + m] = p.x;
            S[base + 32 + m] = p.y;
        }
        sB1[tid] = g_B1[tid];
        sB2[tid] = g_B2[tid];
    }
    __syncthreads();

    const uint32_t aBaseX = sb + OFF_R1 + (w * 32) * ST1 * 2;
    const uint32_t aBaseH = sb + OFF_R1 + (w * 32) * ST2 * 2;
    const uint32_t wB = sb + OFF_R2;

    // ================= layer 1 =================
    float h1[2][16][4];
#pragma unroll
    for (int rt = 0; rt < 2; rt++)
#pragma unroll
        for (int ct = 0; ct < 16; ct++)
#pragma unroll
            for (int e = 0; e < 4; e++) h1[rt][ct][e] = 0.0f;

    for (int k = 0; k < 4; k++) {
        // stage W1 panel [o][c hi|lo]
        for (int i = tid; i < 8192; i += 128) {
            int o = i >> 6, c = i & 63;
            uint32_t u = g_W1p[k][o][c];
            __half2 p = *(__half2*)&u;
            S[OFF_R2 / 2 + o * ST1 + c] = p.x;
            S[OFF_R2 / 2 + o * ST1 + 64 + c] = p.y;
        }
        __syncthreads();
        gemm_cm<4, 64, ST1>(aBaseX, wB, zPtr, lane);
        __syncwarp();
        apply_acc(h1, sb + OFF_A + k * 32 * STA * 2, zB, lane);
        __syncthreads();
    }

    // H1 = relu(h1 + b1) -> smem (aliases X region, stride ST2)
#pragma unroll
    for (int rt = 0; rt < 2; rt++)
#pragma unroll
        for (int ct = 0; ct < 16; ct++)
#pragma unroll
            for (int e = 0; e < 4; e++) {
                int n = rt * 16 + (lane >> 2) + ((e >> 1) << 3);
                int o = ct * 8 + ((lane & 3) << 1) + (e & 1);
                float v = fmaxf(h1[rt][ct][e] + sB1[o], 0.0f);
                __half hh = __float2half_rn(v);
                int row = w * 32 + n;
                S[row * ST2 + o] = hh;
                S[row * ST2 + 128 + o] =
                    __float2half_rn(v - __half2float(hh));
            }

    // ================= layer 2 =================
    float h2[2][16][4];
#pragma unroll
    for (int rt = 0; rt < 2; rt++)
#pragma unroll
        for (int ct = 0; ct < 16; ct++)
#pragma unroll
            for (int e = 0; e < 4; e++) h2[rt][ct][e] = 0.0f;

    for (int k2 = 0; k2 < 4; k2++) {
        // stage W2 panel [o2][o hi|lo]
        for (int i = tid; i < 16384; i += 128) {
            int o2 = i >> 7, o = i & 127;
            uint32_t u = g_W2p[k2][o2][o];
            __half2 p = *(__half2*)&u;
            S[OFF_R2 / 2 + o2 * ST2 + o] = p.x;
            S[OFF_R2 / 2 + o2 * ST2 + 128 + o] = p.y;
        }
        __syncthreads();
        gemm_cm<8, 128, ST2>(aBaseH, wB, zPtr, lane);
        __syncwarp();
        apply_acc(h2, sb + OFF_A + k2 * 32 * STA * 2, zB, lane);
        __syncthreads();
    }

    // ---- FC epilogue ----
    float p0 = 0.0f, p1 = 0.0f;
#pragma unroll
    for (int rt = 0; rt < 2; rt++)
#pragma unroll
        for (int ct = 0; ct < 16; ct++)
#pragma unroll
            for (int rh = 0; rh < 2; rh++) {
                int n = rt * 16 + (lane >> 2) + rh * 8;
                int ob = ct * 8 + ((lane & 3) << 1);
                float v0 = fmaxf(h2[rt][ct][rh * 2 + 0] + sB2[ob], 0.0f);
                float v1 = fmaxf(h2[rt][ct][rh * 2 + 1] + sB2[ob + 1], 0.0f);
                float2 f0 = *(const float2*)&fcw[n * 128 + ob];
                float2 f1 = *(const float2*)&fcw[4096 + n * 128 + ob];
                p0 += v0 * f0.x + v1 * f0.y;
                p1 += v0 * f1.x + v1 * f1.y;
            }
#pragma unroll
    for (int off = 16; off > 0; off >>= 1) {
        p0 += __shfl_xor_sync(0xFFFFFFFFu, p0, off);
        p1 += __shfl_xor_sync(0xFFFFFFFFu, p1, off);
    }
    if (lane == 0) {
        int b = blockIdx.x * 4 + w;
        out[b * 2 + 0] = p0 + fcb[0];
        out[b * 2 + 1] = p1 + fcb[1];
    }
}

// ------------------------------------------------------------------
extern "C" void kernel_launch(void* const* d_in, const int* in_sizes, int n_in,
                              void* d_out, int out_size) {
    const float* x        = (const float*)d_in[0];
    const float* adj      = (const float*)d_in[1];
    const float* adj_bias = (const float*)d_in[2];
    const float* w1       = (const float*)d_in[3];
    const float* b1       = (const float*)d_in[4];
    const float* w2       = (const float*)d_in[5];
    const float* b2       = (const float*)d_in[6];
    const float* fc_w     = (const float*)d_in[7];
    const float* fc_b     = (const float*)d_in[8];
    float* out = (float*)d_out;

    const int B = in_sizes[0] / (NNODE * CIN);

    static int configured = 0;
    cudaFuncSetAttribute(dgcnn_mma_kernel,
                         cudaFuncAttributeMaxDynamicSharedMemorySize,
                         SMEM_TOTAL);
    (void)configured;

    precompute_kernel<<<1, 1024>>>(adj, adj_bias, w1, b1, w2, b2);
    dgcnn_mma_kernel<<<B / 4, 128, SMEM_TOTAL>>>(x, fc_w, fc_b, out);
}

// round 5
// speedup vs baseline: 2.0095x; 1.2476x over previous
#include <cuda_runtime.h>
#include <cuda_fp16.h>
#include <cstdint>

#define NNODE 32
#define CIN   60
#define HID   128
#define KCH   5

// ---- packed hi/lo fp16 constants ----
__device__ uint32_t g_W1p[4][128][64];    // [k][o][c]  = w1[(c*5+k+1)*128+o]
__device__ uint32_t g_W2p[4][128][128];   // [k][o2][o] = w2[(o*5+k+1)*128+o2]
__device__ uint32_t g_Ap[4][32][32];      // A1=I, A2=L, A3=2L^2-I, A4=2L*A3-L
__device__ float    g_B1[128];
__device__ float    g_B2[128];

__device__ __forceinline__ uint32_t packhl(float v) {
    __half h = __float2half_rn(v);
    __half l = __float2half_rn(v - __half2float(h));
    return (uint32_t)__half_as_ushort(h) | ((uint32_t)__half_as_ushort(l) << 16);
}

// ------------------------------------------------------------------
__global__ void precompute_kernel(const float* __restrict__ adj,
                                  const float* __restrict__ adj_bias,
                                  const float* __restrict__ w1,
                                  const float* __restrict__ b1,
                                  const float* __restrict__ w2,
                                  const float* __restrict__ b2) {
    __shared__ float a[NNODE][NNODE];
    __shared__ float L[NNODE][NNODE];
    __shared__ float A3[NNODE][NNODE];
    __shared__ float dre[NNODE];

    int tid = threadIdx.x;
    int n = tid >> 5, m = tid & 31;

    float bias = adj_bias[0];
    a[n][m] = fmaxf(adj[n * NNODE + m] + bias, 0.0f);
    __syncthreads();
    if (m == 0) {
        float s = 0.0f;
        for (int j = 0; j < NNODE; j++) s += a[n][j];
        dre[n] = 1.0f / sqrtf(s + 1e-5f);
    }
    __syncthreads();
    L[n][m] = (n == m ? 1.0f : 0.0f) - dre[n] * a[n][m] * dre[m];
    __syncthreads();
    float s = 0.0f;
    for (int j = 0; j < NNODE; j++) s += L[n][j] * L[j][m];
    A3[n][m] = 2.0f * s - (n == m ? 1.0f : 0.0f);
    __syncthreads();
    float s2 = 0.0f;
    for (int j = 0; j < NNODE; j++) s2 += L[n][j] * A3[j][m];
    float a4 = 2.0f * s2 - L[n][m];

    g_Ap[0][n][m] = packhl(n == m ? 1.0f : 0.0f);
    g_Ap[1][n][m] = packhl(L[n][m]);
    g_Ap[2][n][m] = packhl(A3[n][m]);
    g_Ap[3][n][m] = packhl(a4);

    for (int idx = tid; idx < 4 * 128 * 64; idx += blockDim.x) {
        int k = idx >> 13, r = idx & 8191;
        int o = r >> 6, c = r & 63;
        float v = (c < CIN) ? w1[(c * KCH + k + 1) * HID + o] : 0.0f;
        g_W1p[k][o][c] = packhl(v);
    }
    for (int idx = tid; idx < 4 * 128 * 128; idx += blockDim.x) {
        int k = idx >> 14, r = idx & 16383;
        int o2 = r >> 7, o = r & 127;
        g_W2p[k][o2][o] = packhl(w2[(o * KCH + k + 1) * HID + o2]);
    }
    if (tid < HID) {
        float s1 = b1[tid];
        for (int c = 0; c < CIN; c++) s1 += w1[(c * KCH) * HID + tid];
        g_B1[tid] = s1;
        float sb = b2[tid];
        for (int c = 0; c < HID; c++) sb += w2[(c * KCH) * HID + tid];
        g_B2[tid] = sb;
    }
}

// ------------------------------------------------------------------
__device__ __forceinline__ uint32_t smem_u32(const void* p) {
    uint32_t a;
    asm("{ .reg .u64 t; cvta.to.shared.u64 t, %1; cvt.u32.u64 %0, t; }"
        : "=r"(a) : "l"(p));
    return a;
}
__device__ __forceinline__ void ldsm4(uint32_t* r, uint32_t addr) {
    asm volatile("ldmatrix.sync.aligned.m8n8.x4.shared.b16 {%0,%1,%2,%3}, [%4];\n"
                 : "=r"(r[0]), "=r"(r[1]), "=r"(r[2]), "=r"(r[3]) : "r"(addr));
}
__device__ __forceinline__ void mma16816(float* d, const uint32_t* a,
                                         uint32_t b0, uint32_t b1) {
    asm volatile(
        "mma.sync.aligned.m16n8k16.row.col.f32.f16.f16.f32 "
        "{%0,%1,%2,%3},{%4,%5,%6,%7},{%8,%9},{%0,%1,%2,%3};\n"
        : "+f"(d[0]), "+f"(d[1]), "+f"(d[2]), "+f"(d[3])
        : "r"(a[0]), "r"(a[1]), "r"(a[2]), "r"(a[3]), "r"(b0), "r"(b1));
}

// ---- smem strides (halfs) ----
#define ST1 136   // X/W1 panels: [row][hi 0..63 | lo 64..127 | pad]
#define ST2 264   // H1/W2 panels: [row][hi 0..127 | lo 128..255 | pad]
#define STZ 72    // Z: [o][m-hi 0..31 | m-lo 32..63 | pad]
#define STA 72

// ---- smem regions (bytes) ----
#define OFF_R1 0        // layer1: Xs [128][ST1] | layer2: H1 [128][ST2]
#define OFF_R2 67584    // W panels [128][ST1/ST2]
#define OFF_Z  135168   // per-batch 18432 B : [128][STZ]
#define OFF_A  208896   // [4][32][STA]
#define OFF_B1 227328
#define OFF_B2 227840
#define OFF_RED 228352  // 16*2 floats
#define SMEM_TOTAL 228480

// channel-mix GEMM, N-quarter hf: D[32 x 32] (o cols hf*32..), 3 passes,
// transpose-store hi/lo into zPtr[o][m].
template <int NCH, int SEG, int STRD>
__device__ __forceinline__ void gemm_cm(uint32_t aBase, uint32_t bBase,
                                        __half* zPtr, int lane, int hf) {
    const uint32_t lrow = (uint32_t)(lane & 15);
    const uint32_t lcol = (uint32_t)((lane >> 4) << 3);
    float d[2][4][4];
#pragma unroll
    for (int rt = 0; rt < 2; rt++)
#pragma unroll
        for (int ct = 0; ct < 4; ct++)
#pragma unroll
            for (int e = 0; e < 4; e++) d[rt][ct][e] = 0.0f;

    for (int p = 0; p < 3; p++) {
        const int aoff = (p == 2) ? SEG : 0;
        const int boff = (p == 1) ? SEG : 0;
        for (int c = 0; c < NCH; c++) {
            const int ka = aoff + c * 16, kb = boff + c * 16;
            uint32_t A0[4], A1[4];
            ldsm4(A0, aBase + ((0 + lrow) * STRD + ka + lcol) * 2);
            ldsm4(A1, aBase + ((16 + lrow) * STRD + ka + lcol) * 2);
#pragma unroll
            for (int n2 = 0; n2 < 2; n2++) {
                const int nt = hf * 4 + n2 * 2;
                uint32_t Bf[4];
                ldsm4(Bf, bBase + ((nt * 8 + lrow) * STRD + kb + lcol) * 2);
                mma16816(d[0][n2 * 2 + 0], A0, Bf[0], Bf[2]);
                mma16816(d[0][n2 * 2 + 1], A0, Bf[1], Bf[3]);
                mma16816(d[1][n2 * 2 + 0], A1, Bf[0], Bf[2]);
                mma16816(d[1][n2 * 2 + 1], A1, Bf[1], Bf[3]);
            }
        }
    }
#pragma unroll
    for (int rt = 0; rt < 2; rt++)
#pragma unroll
        for (int ct = 0; ct < 4; ct++)
#pragma unroll
            for (int e = 0; e < 4; e++) {
                int m = rt * 16 + (lane >> 2) + ((e >> 1) << 3);
                int o = (hf * 4 + ct) * 8 + ((lane & 3) << 1) + (e & 1);
                float v = d[rt][ct][e];
                __half hh = __float2half_rn(v);
                zPtr[o * STZ + m] = hh;
                zPtr[o * STZ + 32 + m] = __float2half_rn(v - __half2float(hh));
            }
}

// A-apply (o-quarter wb): acc[32n x 32o] += A_k x Z
__device__ __forceinline__ void apply_acc(float (&acc)[2][4][4],
                                          uint32_t aBase, uint32_t bBase,
                                          int lane, int wb) {
    const uint32_t lrow = (uint32_t)(lane & 15);
    const uint32_t lcol = (uint32_t)((lane >> 4) << 3);
    for (int p = 0; p < 3; p++) {
        const int aoff = (p == 2) ? 32 : 0;
        const int boff = (p == 1) ? 32 : 0;
        for (int c = 0; c < 2; c++) {
            const int ka = aoff + c * 16, kb = boff + c * 16;
            uint32_t A0[4], A1[4];
            ldsm4(A0, aBase + ((0 + lrow) * STA + ka + lcol) * 2);
            ldsm4(A1, aBase + ((16 + lrow) * STA + ka + lcol) * 2);
#pragma unroll
            for (int n2 = 0; n2 < 2; n2++) {
                const int n2g = wb * 2 + n2;
                uint32_t Bf[4];
                ldsm4(Bf, bBase + ((n2g * 16 + lrow) * STZ + kb + lcol) * 2);
                mma16816(acc[0][n2 * 2 + 0], A0, Bf[0], Bf[2]);
                mma16816(acc[0][n2 * 2 + 1], A0, Bf[1], Bf[3]);
                mma16816(acc[1][n2 * 2 + 0], A1, Bf[0], Bf[2]);
                mma16816(acc[1][n2 * 2 + 1], A1, Bf[1], Bf[3]);
            }
        }
    }
}

// ------------------------------------------------------------------
__global__ __launch_bounds__(512, 1) void dgcnn_mma_kernel(
    const float* __restrict__ x,
    const float* __restrict__ fcw,
    const float* __restrict__ fcb,
    float* __restrict__ out) {

    extern __shared__ char smem[];
    __half* S = (__half*)smem;
    const uint32_t sb = smem_u32(smem);
    const int tid = threadIdx.x;
    const int w = tid >> 5, lane = tid & 31;
    const int bp = w >> 2, wb = w & 3;       // batch, o-quarter

    float* sB1 = (float*)(smem + OFF_B1);
    float* sB2 = (float*)(smem + OFF_B2);
    float* red = (float*)(smem + OFF_RED);
    __half* zPtr = (__half*)(smem + OFF_Z + bp * 18432);
    const uint32_t zB = sb + OFF_Z + bp * 18432;

    // ---- prologue ----
    for (int i = tid; i < 128 * ST1 / 2; i += 512) ((uint32_t*)smem)[i] = 0;
    __syncthreads();
    {
        const float* xb = x + (size_t)blockIdx.x * 128 * CIN;
        for (int i = tid; i < 128 * CIN; i += 512) {
            int row = i / CIN, c = i - row * CIN;
            float v = xb[i];
            __half h = __float2half_rn(v);
            S[row * ST1 + c] = h;
            S[row * ST1 + 64 + c] = __float2half_rn(v - __half2float(h));
        }
        for (int i = tid; i < 4096; i += 512) {
            int k = i >> 10, n = (i >> 5) & 31, m = i & 31;
            uint32_t u = g_Ap[k][n][m];
            __half2 p = *(__half2*)&u;
            int base = OFF_A / 2 + (k * 32 + n) * STA;
            S[base + m] = p.x;
            S[base + 32 + m] = p.y;
        }
        if (tid < 128) { sB1[tid] = g_B1[tid]; sB2[tid] = g_B2[tid]; }
    }
    __syncthreads();

    const uint32_t aBaseX = sb + OFF_R1 + (bp * 32) * ST1 * 2;
    const uint32_t aBaseH = sb + OFF_R1 + (bp * 32) * ST2 * 2;
    const uint32_t wB = sb + OFF_R2;

    // ================= layer 1 =================
    float h1[2][4][4];
#pragma unroll
    for (int rt = 0; rt < 2; rt++)
#pragma unroll
        for (int ct = 0; ct < 4; ct++)
#pragma unroll
            for (int e = 0; e < 4; e++) h1[rt][ct][e] = 0.0f;

    for (int k = 0; k < 4; k++) {
        for (int i = tid; i < 8192; i += 512) {
            int o = i >> 6, c = i & 63;
            uint32_t u = g_W1p[k][o][c];
            __half2 p = *(__half2*)&u;
            S[OFF_R2 / 2 + o * ST1 + c] = p.x;
            S[OFF_R2 / 2 + o * ST1 + 64 + c] = p.y;
        }
        __syncthreads();
        gemm_cm<4, 64, ST1>(aBaseX, wB, zPtr, lane, wb);
        __syncthreads();
        apply_acc(h1, sb + OFF_A + k * 32 * STA * 2, zB, lane, wb);
    }
    __syncthreads();

    // H1 = relu(h1 + b1) -> smem (aliases X region, stride ST2)
#pragma unroll
    for (int rt = 0; rt < 2; rt++)
#pragma unroll
        for (int ct = 0; ct < 4; ct++)
#pragma unroll
            for (int e = 0; e < 4; e++) {
                int n = rt * 16 + (lane >> 2) + ((e >> 1) << 3);
                int o = wb * 32 + ct * 8 + ((lane & 3) << 1) + (e & 1);
                float v = fmaxf(h1[rt][ct][e] + sB1[o], 0.0f);
                __half hh = __float2half_rn(v);
                int row = bp * 32 + n;
                S[row * ST2 + o] = hh;
                S[row * ST2 + 128 + o] = __float2half_rn(v - __half2float(hh));
            }

    // ================= layer 2 =================
    float h2[2][4][4];
#pragma unroll
    for (int rt = 0; rt < 2; rt++)
#pragma unroll
        for (int ct = 0; ct < 4; ct++)
#pragma unroll
            for (int e = 0; e < 4; e++) h2[rt][ct][e] = 0.0f;

    for (int k2 = 0; k2 < 4; k2++) {
        for (int i = tid; i < 16384; i += 512) {
            int o2 = i >> 7, o = i & 127;
            uint32_t u = g_W2p[k2][o2][o];
            __half2 p = *(__half2*)&u;
            S[OFF_R2 / 2 + o2 * ST2 + o] = p.x;
            S[OFF_R2 / 2 + o2 * ST2 + 128 + o] = p.y;
        }
        __syncthreads();
        gemm_cm<8, 128, ST2>(aBaseH, wB, zPtr, lane, wb);
        __syncthreads();
        apply_acc(h2, sb + OFF_A + k2 * 32 * STA * 2, zB, lane, wb);
        __syncthreads();
    }

    // ---- FC epilogue (per-warp o-quarter, cross-warp sum) ----
    float p0 = 0.0f, p1 = 0.0f;
#pragma unroll
    for (int rt = 0; rt < 2; rt++)
#pragma unroll
        for (int ct = 0; ct < 4; ct++)
#pragma unroll
            for (int rh = 0; rh < 2; rh++) {
                int n = rt * 16 + (lane >> 2) + rh * 8;
                int ob = wb * 32 + ct * 8 + ((lane & 3) << 1);
                float v0 = fmaxf(h2[rt][ct][rh * 2 + 0] + sB2[ob], 0.0f);
                float v1 = fmaxf(h2[rt][ct][rh * 2 + 1] + sB2[ob + 1], 0.0f);
                float2 f0 = *(const float2*)&fcw[n * 128 + ob];
                float2 f1 = *(const float2*)&fcw[4096 + n * 128 + ob];
                p0 += v0 * f0.x + v1 * f0.y;
                p1 += v0 * f1.x + v1 * f1.y;
            }
#pragma unroll
    for (int off = 16; off > 0; off >>= 1) {
        p0 += __shfl_xor_sync(0xFFFFFFFFu, p0, off);
        p1 += __shfl_xor_sync(0xFFFFFFFFu, p1, off);
    }
    if (lane == 0) { red[w * 2] = p0; red[w * 2 + 1] = p1; }
    __syncthreads();
    if (tid < 8) {
        int b2 = tid >> 1, c = tid & 1;
        float s = red[(b2 * 4 + 0) * 2 + c] + red[(b2 * 4 + 1) * 2 + c] +
                  red[(b2 * 4 + 2) * 2 + c] + red[(b2 * 4 + 3) * 2 + c];
        out[(blockIdx.x * 4 + b2) * 2 + c] = s + fcb[c];
    }
}

// ------------------------------------------------------------------
extern "C" void kernel_launch(void* const* d_in, const int* in_sizes, int n_in,
                              void* d_out, int out_size) {
    const float* x        = (const float*)d_in[0];
    const float* adj      = (const float*)d_in[1];
    const float* adj_bias = (const float*)d_in[2];
    const float* w1       = (const float*)d_in[3];
    const float* b1       = (const float*)d_in[4];
    const float* w2       = (const float*)d_in[5];
    const float* b2       = (const float*)d_in[6];
    const float* fc_w     = (const float*)d_in[7];
    const float* fc_b     = (const float*)d_in[8];
    float* out = (float*)d_out;

    const int B = in_sizes[0] / (NNODE * CIN);

    cudaFuncSetAttribute(dgcnn_mma_kernel,
                         cudaFuncAttributeMaxDynamicSharedMemorySize,
                         SMEM_TOTAL);

    precompute_kernel<<<1, 1024>>>(adj, adj_bias, w1, b1, w2, b2);
    dgcnn_mma_kernel<<<B / 4, 512, SMEM_TOTAL>>>(x, fc_w, fc_b, out);
}

// round 6
// speedup vs baseline: 2.2210x; 1.1052x over previous
#include <cuda_runtime.h>
#include <cuda_fp16.h>
#include <cstdint>

#define NNODE 32
#define CIN   60
#define HID   128
#define KCH   5

// ---- packed hi/lo fp16 constants ----
__device__ uint32_t g_W1p[4][128][64];    // [k][o][c]  = w1[(c*5+k+1)*128+o]
__device__ uint32_t g_W2p[4][128][128];   // [k][o2][o] = w2[(o*5+k+1)*128+o2]
__device__ uint32_t g_Ap[4][32][32];      // A1=I, A2=L, A3=2L^2-I, A4=2L*A3-L
__device__ float    g_B1[128];
__device__ float    g_B2[128];

__device__ __forceinline__ uint32_t packhl(float v) {
    __half h = __float2half_rn(v);
    __half l = __float2half_rn(v - __half2float(h));
    return (uint32_t)__half_as_ushort(h) | ((uint32_t)__half_as_ushort(l) << 16);
}

// ------------------------------------------------------------------
__global__ void precompute_kernel(const float* __restrict__ adj,
                                  const float* __restrict__ adj_bias,
                                  const float* __restrict__ w1,
                                  const float* __restrict__ b1,
                                  const float* __restrict__ w2,
                                  const float* __restrict__ b2) {
    __shared__ float a[NNODE][NNODE];
    __shared__ float L[NNODE][NNODE];
    __shared__ float A3[NNODE][NNODE];
    __shared__ float dre[NNODE];

    int tid = threadIdx.x;
    int n = tid >> 5, m = tid & 31;

    float bias = adj_bias[0];
    a[n][m] = fmaxf(adj[n * NNODE + m] + bias, 0.0f);
    __syncthreads();
    if (m == 0) {
        float s = 0.0f;
        for (int j = 0; j < NNODE; j++) s += a[n][j];
        dre[n] = 1.0f / sqrtf(s + 1e-5f);
    }
    __syncthreads();
    L[n][m] = (n == m ? 1.0f : 0.0f) - dre[n] * a[n][m] * dre[m];
    __syncthreads();
    float s = 0.0f;
    for (int j = 0; j < NNODE; j++) s += L[n][j] * L[j][m];
    A3[n][m] = 2.0f * s - (n == m ? 1.0f : 0.0f);
    __syncthreads();
    float s2 = 0.0f;
    for (int j = 0; j < NNODE; j++) s2 += L[n][j] * A3[j][m];
    float a4 = 2.0f * s2 - L[n][m];

    g_Ap[0][n][m] = packhl(n == m ? 1.0f : 0.0f);
    g_Ap[1][n][m] = packhl(L[n][m]);
    g_Ap[2][n][m] = packhl(A3[n][m]);
    g_Ap[3][n][m] = packhl(a4);

    for (int idx = tid; idx < 4 * 128 * 64; idx += blockDim.x) {
        int k = idx >> 13, r = idx & 8191;
        int o = r >> 6, c = r & 63;
        float v = (c < CIN) ? w1[(c * KCH + k + 1) * HID + o] : 0.0f;
        g_W1p[k][o][c] = packhl(v);
    }
    for (int idx = tid; idx < 4 * 128 * 128; idx += blockDim.x) {
        int k = idx >> 14, r = idx & 16383;
        int o2 = r >> 7, o = r & 127;
        g_W2p[k][o2][o] = packhl(w2[(o * KCH + k + 1) * HID + o2]);
    }
    if (tid < HID) {
        float s1 = b1[tid];
        for (int c = 0; c < CIN; c++) s1 += w1[(c * KCH) * HID + tid];
        g_B1[tid] = s1;
        float sb = b2[tid];
        for (int c = 0; c < HID; c++) sb += w2[(c * KCH) * HID + tid];
        g_B2[tid] = sb;
    }
}

// ------------------------------------------------------------------
__device__ __forceinline__ uint32_t smem_u32(const void* p) {
    uint32_t a;
    asm("{ .reg .u64 t; cvta.to.shared.u64 t, %1; cvt.u32.u64 %0, t; }"
        : "=r"(a) : "l"(p));
    return a;
}
__device__ __forceinline__ void ldsm4(uint32_t* r, uint32_t addr) {
    asm volatile("ldmatrix.sync.aligned.m8n8.x4.shared.b16 {%0,%1,%2,%3}, [%4];\n"
                 : "=r"(r[0]), "=r"(r[1]), "=r"(r[2]), "=r"(r[3]) : "r"(addr));
}
__device__ __forceinline__ void mma16816(float* d, const uint32_t* a,
                                         uint32_t b0, uint32_t b1) {
    asm volatile(
        "mma.sync.aligned.m16n8k16.row.col.f32.f16.f16.f32 "
        "{%0,%1,%2,%3},{%4,%5,%6,%7},{%8,%9},{%0,%1,%2,%3};\n"
        : "+f"(d[0]), "+f"(d[1]), "+f"(d[2]), "+f"(d[3])
        : "r"(a[0]), "r"(a[1]), "r"(a[2]), "r"(a[3]), "r"(b0), "r"(b1));
}
__device__ __forceinline__ uint32_t pack2(float x, float y) {
    __half2 h = __float22half2_rn(make_float2(x, y));
    return *(uint32_t*)&h;
}

// ---- smem strides (halfs) ----
#define ST1 136   // X/W1 panels: [row][hi 0..63 | lo 64..127 | pad]
#define ST2 264   // H1/W2 panels: [row][hi 0..127 | lo 128..255 | pad]
#define STA 72    // A: [n][Ah 0..31 | Al 32..63 | pad]

// ---- smem regions (bytes) ----
#define OFF_R1  0        // layer1: Xs [128][ST1] | layer2: H1 [128][ST2]
#define OFF_R2  67584    // W panels
#define OFF_A   135168   // [4][32][STA]
#define OFF_B1  153600
#define OFF_B2  154112
#define OFF_FC  154624   // [2][128][34] f32
#define OFF_RED 189440
#define SMEM_TOTAL 189568

// GEMM-1: d[2 ot][4 mt][4] = Wpanel(rows o, warp quarter) x X/H(rows m).
// 3 compensated passes: (Wh,Xh), (Wl,Xh), (Wh,Xl).
template <int NCH, int SEG, int STRD>
__device__ __forceinline__ void gemm_regs(uint32_t aBase, uint32_t bBase,
                                          float (&d)[2][4][4], int lane) {
    const uint32_t lrow = (uint32_t)(lane & 15);
    const uint32_t lcol = (uint32_t)((lane >> 4) << 3);
#pragma unroll
    for (int t = 0; t < 2; t++)
#pragma unroll
        for (int j = 0; j < 4; j++)
#pragma unroll
            for (int e = 0; e < 4; e++) d[t][j][e] = 0.0f;

    for (int p = 0; p < 3; p++) {
        const int aoff = (p == 1) ? SEG : 0;
        const int boff = (p == 2) ? SEG : 0;
#pragma unroll
        for (int c = 0; c < NCH; c++) {
            const int ka = aoff + c * 16, kb = boff + c * 16;
            uint32_t A0[4], A1[4];
            ldsm4(A0, aBase + (lrow * STRD + ka + lcol) * 2);
            ldsm4(A1, aBase + ((16 + lrow) * STRD + ka + lcol) * 2);
#pragma unroll
            for (int np = 0; np < 2; np++) {
                uint32_t Bf[4];
                ldsm4(Bf, bBase + ((np * 16 + lrow) * STRD + kb + lcol) * 2);
                mma16816(d[0][np * 2 + 0], A0, Bf[0], Bf[2]);
                mma16816(d[0][np * 2 + 1], A0, Bf[1], Bf[3]);
                mma16816(d[1][np * 2 + 0], A1, Bf[0], Bf[2]);
                mma16816(d[1][np * 2 + 1], A1, Bf[1], Bf[3]);
            }
        }
    }
}

// A-apply, register-chained: acc[o][n] += Z^T x Abig_k^T.
// Z fragments come straight from d (C->A fragment conversion).
__device__ __forceinline__ void apply_chain(float (&acc)[2][4][4],
                                            const float (&d)[2][4][4],
                                            uint32_t sAk, int lane) {
    const uint32_t lrow = (uint32_t)(lane & 15);
    const uint32_t lcol = (uint32_t)((lane >> 4) << 3);
    // pack hi/lo fragments
    uint32_t zh2[2][4][2], zl2[2][4][2];
#pragma unroll
    for (int t = 0; t < 2; t++)
#pragma unroll
        for (int j = 0; j < 4; j++) {
#pragma unroll
            for (int pr = 0; pr < 2; pr++) {
                float v0 = d[t][j][pr * 2 + 0], v1 = d[t][j][pr * 2 + 1];
                uint32_t zh = pack2(v0, v1);
                __half2 hh = *(__half2*)&zh;
                float2 hf = __half22float2(hh);
                zh2[t][j][pr] = zh;
                zl2[t][j][pr] = pack2(v0 - hf.x, v1 - hf.y);
            }
        }
#pragma unroll
    for (int kh = 0; kh < 2; kh++) {
        uint32_t BH[2][4], BL[2][4];
#pragma unroll
        for (int np = 0; np < 2; np++) {
            ldsm4(BH[np], sAk + ((np * 16 + lrow) * STA + kh * 16 + lcol) * 2);
            ldsm4(BL[np], sAk + ((np * 16 + lrow) * STA + 32 + kh * 16 + lcol) * 2);
        }
#pragma unroll
        for (int t = 0; t < 2; t++) {
            uint32_t Ah_[4] = {zh2[t][2 * kh][0], zh2[t][2 * kh][1],
                               zh2[t][2 * kh + 1][0], zh2[t][2 * kh + 1][1]};
            uint32_t Al_[4] = {zl2[t][2 * kh][0], zl2[t][2 * kh][1],
                               zl2[t][2 * kh + 1][0], zl2[t][2 * kh + 1][1]};
#pragma unroll
            for (int np = 0; np < 2; np++) {
                mma16816(acc[t][np * 2 + 0], Ah_, BH[np][0], BH[np][2]);
                mma16816(acc[t][np * 2 + 1], Ah_, BH[np][1], BH[np][3]);
                mma16816(acc[t][np * 2 + 0], Al_, BH[np][0], BH[np][2]);
                mma16816(acc[t][np * 2 + 1], Al_, BH[np][1], BH[np][3]);
                mma16816(acc[t][np * 2 + 0], Ah_, BL[np][0], BL[np][2]);
                mma16816(acc[t][np * 2 + 1], Ah_, BL[np][1], BL[np][3]);
            }
        }
    }
}

// ------------------------------------------------------------------
__global__ __launch_bounds__(512, 1) void dgcnn_mma_kernel(
    const float* __restrict__ x,
    const float* __restrict__ fcw,
    const float* __restrict__ fcb,
    float* __restrict__ out) {

    extern __shared__ char smem[];
    __half* S = (__half*)smem;
    const uint32_t sb = smem_u32(smem);
    const int tid = threadIdx.x;
    const int w = tid >> 5, lane = tid & 31;
    const int bp = w >> 2, wb = w & 3;       // batch, o-quarter

    float* sB1 = (float*)(smem + OFF_B1);
    float* sB2 = (float*)(smem + OFF_B2);
    float* sFC = (float*)(smem + OFF_FC);
    float* red = (float*)(smem + OFF_RED);

    // ---- prologue ----
    for (int i = tid; i < 128 * ST1 / 2; i += 512) ((uint32_t*)smem)[i] = 0;
    __syncthreads();
    {
        const float* xb = x + (size_t)blockIdx.x * 128 * CIN;
        for (int i = tid; i < 128 * CIN; i += 512) {
            int row = i / CIN, c = i - row * CIN;
            float v = xb[i];
            __half h = __float2half_rn(v);
            S[row * ST1 + c] = h;
            S[row * ST1 + 64 + c] = __float2half_rn(v - __half2float(h));
        }
        for (int i = tid; i < 4096; i += 512) {
            int k = i >> 10, n = (i >> 5) & 31, m = i & 31;
            uint32_t u = g_Ap[k][n][m];
            __half2 p = *(__half2*)&u;
            int base = OFF_A / 2 + (k * 32 + n) * STA;
            S[base + m] = p.x;
            S[base + 32 + m] = p.y;
        }
        for (int i = tid; i < 8192; i += 512) {
            int cc = i >> 12, r = i & 4095;
            int n = r >> 7, o2 = r & 127;
            sFC[(cc * 128 + o2) * 34 + n] = fcw[i];
        }
        if (tid < 128) { sB1[tid] = g_B1[tid]; sB2[tid] = g_B2[tid]; }
    }
    __syncthreads();

    const uint32_t wPanel1 = sb + OFF_R2 + (wb * 32) * ST1 * 2;
    const uint32_t wPanel2 = sb + OFF_R2 + (wb * 32) * ST2 * 2;
    const uint32_t bX = sb + OFF_R1 + (bp * 32) * ST1 * 2;
    const uint32_t bH = sb + OFF_R1 + (bp * 32) * ST2 * 2;

    // ================= layer 1 =================
    float acc[2][4][4];
#pragma unroll
    for (int t = 0; t < 2; t++)
#pragma unroll
        for (int j = 0; j < 4; j++)
#pragma unroll
            for (int e = 0; e < 4; e++) acc[t][j][e] = 0.0f;

    for (int k = 0; k < 4; k++) {
        for (int i = tid; i < 8192; i += 512) {
            int o = i >> 6, c = i & 63;
            uint32_t u = g_W1p[k][o][c];
            __half2 p = *(__half2*)&u;
            S[OFF_R2 / 2 + o * ST1 + c] = p.x;
            S[OFF_R2 / 2 + o * ST1 + 64 + c] = p.y;
        }
        __syncthreads();
        float d[2][4][4];
        gemm_regs<4, 64, ST1>(wPanel1, bX, d, lane);
        if (k == 0) {
#pragma unroll
            for (int t = 0; t < 2; t++)
#pragma unroll
                for (int j = 0; j < 4; j++)
#pragma unroll
                    for (int e = 0; e < 4; e++) acc[t][j][e] += d[t][j][e];
        } else {
            apply_chain(acc, d, sb + OFF_A + k * 32 * STA * 2, lane);
        }
        __syncthreads();
    }

    // H1 = relu(acc + b1) -> smem (aliases X region, stride ST2)
#pragma unroll
    for (int t = 0; t < 2; t++)
#pragma unroll
        for (int j = 0; j < 4; j++)
#pragma unroll
            for (int e = 0; e < 4; e++) {
                int o = wb * 32 + t * 16 + (lane >> 2) + ((e >> 1) << 3);
                int n = j * 8 + ((lane & 3) << 1) + (e & 1);
                float v = fmaxf(acc[t][j][e] + sB1[o], 0.0f);
                __half hh = __float2half_rn(v);
                int row = bp * 32 + n;
                S[row * ST2 + o] = hh;
                S[row * ST2 + 128 + o] = __float2half_rn(v - __half2float(hh));
            }
    __syncthreads();

    // ================= layer 2 =================
#pragma unroll
    for (int t = 0; t < 2; t++)
#pragma unroll
        for (int j = 0; j < 4; j++)
#pragma unroll
            for (int e = 0; e < 4; e++) acc[t][j][e] = 0.0f;

    for (int k2 = 0; k2 < 4; k2++) {
        for (int i = tid; i < 16384; i += 512) {
            int o2 = i >> 7, o = i & 127;
            uint32_t u = g_W2p[k2][o2][o];
            __half2 p = *(__half2*)&u;
            S[OFF_R2 / 2 + o2 * ST2 + o] = p.x;
            S[OFF_R2 / 2 + o2 * ST2 + 128 + o] = p.y;
        }
        __syncthreads();
        float d[2][4][4];
        gemm_regs<8, 128, ST2>(wPanel2, bH, d, lane);
        if (k2 == 0) {
#pragma unroll
            for (int t = 0; t < 2; t++)
#pragma unroll
                for (int j = 0; j < 4; j++)
#pragma unroll
                    for (int e = 0; e < 4; e++) acc[t][j][e] += d[t][j][e];
        } else {
            apply_chain(acc, d, sb + OFF_A + k2 * 32 * STA * 2, lane);
        }
        __syncthreads();
    }

    // ---- FC epilogue ----
    float p0 = 0.0f, p1 = 0.0f;
#pragma unroll
    for (int t = 0; t < 2; t++)
#pragma unroll
        for (int j = 0; j < 4; j++)
#pragma unroll
            for (int e = 0; e < 4; e++) {
                int o2 = wb * 32 + t * 16 + (lane >> 2) + ((e >> 1) << 3);
                int n = j * 8 + ((lane & 3) << 1) + (e & 1);
                float v = fmaxf(acc[t][j][e] + sB2[o2], 0.0f);
                p0 += v * sFC[o2 * 34 + n];
                p1 += v * sFC[(128 + o2) * 34 + n];
            }
#pragma unroll
    for (int off = 16; off > 0; off >>= 1) {
        p0 += __shfl_xor_sync(0xFFFFFFFFu, p0, off);
        p1 += __shfl_xor_sync(0xFFFFFFFFu, p1, off);
    }
    if (lane == 0) { red[w * 2] = p0; red[w * 2 + 1] = p1; }
    __syncthreads();
    if (tid < 8) {
        int b2 = tid >> 1, c = tid & 1;
        float s = red[(b2 * 4 + 0) * 2 + c] + red[(b2 * 4 + 1) * 2 + c] +
                  red[(b2 * 4 + 2) * 2 + c] + red[(b2 * 4 + 3) * 2 + c];
        out[(blockIdx.x * 4 + b2) * 2 + c] = s + fcb[c];
    }
}

// ------------------------------------------------------------------
extern "C" void kernel_launch(void* const* d_in, const int* in_sizes, int n_in,
                              void* d_out, int out_size) {
    const float* x        = (const float*)d_in[0];
    const float* adj      = (const float*)d_in[1];
    const float* adj_bias = (const float*)d_in[2];
    const float* w1       = (const float*)d_in[3];
    const float* b1       = (const float*)d_in[4];
    const float* w2       = (const float*)d_in[5];
    const float* b2       = (const float*)d_in[6];
    const float* fc_w     = (const float*)d_in[7];
    const float* fc_b     = (const float*)d_in[8];
    float* out = (float*)d_out;

    const int B = in_sizes[0] / (NNODE * CIN);

    cudaFuncSetAttribute(dgcnn_mma_kernel,
                         cudaFuncAttributeMaxDynamicSharedMemorySize,
                         SMEM_TOTAL);

    precompute_kernel<<<1, 1024>>>(adj, adj_bias, w1, b1, w2, b2);
    dgcnn_mma_kernel<<<B / 4, 512, SMEM_TOTAL>>>(x, fc_w, fc_b, out);
}

// round 8
// speedup vs baseline: 2.8912x; 1.3017x over previous
#include <cuda_runtime.h>
#include <cuda_fp16.h>
#include <cstdint>

#define NNODE 32
#define CIN   60
#define HID   128
#define KCH   5

// ---- device-global packed constants ----
__device__ __align__(16) __half g_W1s[4][128][128]; // [k][o][c hi | 64+c lo]
__device__ __align__(16) __half g_W2s[4][128][128]; // [k][o2][o] hi only
__device__ uint32_t g_Ap[4][32][32];                // packed hi|lo
__device__ float    g_B1[128];
__device__ float    g_B2[128];

__device__ __forceinline__ uint32_t packhl(float v) {
    __half h = __float2half_rn(v);
    __half l = __float2half_rn(v - __half2float(h));
    return (uint32_t)__half_as_ushort(h) | ((uint32_t)__half_as_ushort(l) << 16);
}

// ------------------------------------------------------------------
__global__ void precompute_kernel(const float* __restrict__ adj,
                                  const float* __restrict__ adj_bias,
                                  const float* __restrict__ w1,
                                  const float* __restrict__ b1,
                                  const float* __restrict__ w2,
                                  const float* __restrict__ b2) {
    __shared__ float a[NNODE][NNODE];
    __shared__ float L[NNODE][NNODE];
    __shared__ float A3[NNODE][NNODE];
    __shared__ float dre[NNODE];

    int tid = threadIdx.x;
    int n = tid >> 5, m = tid & 31;

    float bias = adj_bias[0];
    a[n][m] = fmaxf(adj[n * NNODE + m] + bias, 0.0f);
    __syncthreads();
    if (m == 0) {
        float s = 0.0f;
        for (int j = 0; j < NNODE; j++) s += a[n][j];
        dre[n] = 1.0f / sqrtf(s + 1e-5f);
    }
    __syncthreads();
    L[n][m] = (n == m ? 1.0f : 0.0f) - dre[n] * a[n][m] * dre[m];
    __syncthreads();
    float s = 0.0f;
    for (int j = 0; j < NNODE; j++) s += L[n][j] * L[j][m];
    A3[n][m] = 2.0f * s - (n == m ? 1.0f : 0.0f);
    __syncthreads();
    float s2 = 0.0f;
    for (int j = 0; j < NNODE; j++) s2 += L[n][j] * A3[j][m];
    float a4 = 2.0f * s2 - L[n][m];

    g_Ap[0][n][m] = packhl(n == m ? 1.0f : 0.0f);
    g_Ap[1][n][m] = packhl(L[n][m]);
    g_Ap[2][n][m] = packhl(A3[n][m]);
    g_Ap[3][n][m] = packhl(a4);

    // W1 hi|lo packed in smem-row layout
    for (int idx = tid; idx < 4 * 128 * 64; idx += blockDim.x) {
        int k = idx >> 13, r = idx & 8191;
        int o = r >> 6, c = r & 63;
        float v = (c < CIN) ? w1[(c * KCH + k + 1) * HID + o] : 0.0f;
        __half h = __float2half_rn(v);
        g_W1s[k][o][c] = h;
        g_W1s[k][o][64 + c] = __float2half_rn(v - __half2float(h));
    }
    // W2 hi only
    for (int idx = tid; idx < 4 * 128 * 128; idx += blockDim.x) {
        int k = idx >> 14, r = idx & 16383;
        int o2 = r >> 7, o = r & 127;
        g_W2s[k][o2][o] = __float2half_rn(w2[(o * KCH + k + 1) * HID + o2]);
    }
    if (tid < HID) {
        float s1 = b1[tid];
        for (int c = 0; c < CIN; c++) s1 += w1[(c * KCH) * HID + tid];
        g_B1[tid] = s1;
        float sb = b2[tid];
        for (int c = 0; c < HID; c++) sb += w2[(c * KCH) * HID + tid];
        g_B2[tid] = sb;
    }
}

// ------------------------------------------------------------------
__device__ __forceinline__ uint32_t smem_u32(const void* p) {
    uint32_t a;
    asm("{ .reg .u64 t; cvta.to.shared.u64 t, %1; cvt.u32.u64 %0, t; }"
        : "=r"(a) : "l"(p));
    return a;
}
__device__ __forceinline__ void ldsm4(uint32_t* r, uint32_t addr) {
    asm volatile("ldmatrix.sync.aligned.m8n8.x4.shared.b16 {%0,%1,%2,%3}, [%4];\n"
                 : "=r"(r[0]), "=r"(r[1]), "=r"(r[2]), "=r"(r[3]) : "r"(addr));
}
__device__ __forceinline__ void mma16816(float* d, const uint32_t* a,
                                         uint32_t b0, uint32_t b1) {
    asm volatile(
        "mma.sync.aligned.m16n8k16.row.col.f32.f16.f16.f32 "
        "{%0,%1,%2,%3},{%4,%5,%6,%7},{%8,%9},{%0,%1,%2,%3};\n"
        : "+f"(d[0]), "+f"(d[1]), "+f"(d[2]), "+f"(d[3])
        : "r"(a[0]), "r"(a[1]), "r"(a[2]), "r"(a[3]), "r"(b0), "r"(b1));
}
__device__ __forceinline__ uint32_t pack2(float x, float y) {
    __half2 h = __float22half2_rn(make_float2(x, y));
    return *(uint32_t*)&h;
}

// ---- smem strides (halfs) ----
#define ST1 136   // rows: layer1 X [hi 0..63|lo 64..127|pad]; layer2 H [hi 0..127|pad]
#define STA 72    // A: [n][Ah 0..31 | Al 32..63 | pad]

// ---- smem regions (bytes), per CTA ----
#define OFF_R1  0        // [64][ST1]  X (l1) / H (l2)       17408
#define OFF_R2  17408    // [128][ST1] W panels              34816
#define OFF_A   52224    // [4][32][STA]                     18432
#define OFF_B1  70656
#define OFF_B2  71168
#define OFF_FC  71680    // [2][128][34] f32                 34816
#define OFF_RED 106496
#define SMEM_TOTAL 106624

// GEMM-1: d[2 ot][4 nt][4] = Wpanel(rows o, quarter wb) x X/H(rows n).
// NPASS=3: (Wh,Xh),(Wl,Xh),(Wh,Xl); NPASS=1: (Wh,Xh).
template <int NCH, int SEG, int NPASS>
__device__ __forceinline__ void gemm_regs(uint32_t aBase, uint32_t bBase,
                                          float (&d)[2][4][4], int lane) {
    const uint32_t lrow = (uint32_t)(lane & 15);
    const uint32_t lcol = (uint32_t)((lane >> 4) << 3);
#pragma unroll
    for (int t = 0; t < 2; t++)
#pragma unroll
        for (int j = 0; j < 4; j++)
#pragma unroll
            for (int e = 0; e < 4; e++) d[t][j][e] = 0.0f;

#pragma unroll
    for (int p = 0; p < NPASS; p++) {
        const int aoff = (p == 1) ? SEG : 0;
        const int boff = (p == 2) ? SEG : 0;
#pragma unroll
        for (int c = 0; c < NCH; c++) {
            const int ka = aoff + c * 16, kb = boff + c * 16;
            uint32_t A0[4], A1[4];
            ldsm4(A0, aBase + (lrow * ST1 + ka + lcol) * 2);
            ldsm4(A1, aBase + ((16 + lrow) * ST1 + ka + lcol) * 2);
#pragma unroll
            for (int np = 0; np < 2; np++) {
                uint32_t Bf[4];
                ldsm4(Bf, bBase + ((np * 16 + lrow) * ST1 + kb + lcol) * 2);
                mma16816(d[0][np * 2 + 0], A0, Bf[0], Bf[2]);
                mma16816(d[0][np * 2 + 1], A0, Bf[1], Bf[3]);
                mma16816(d[1][np * 2 + 0], A1, Bf[0], Bf[2]);
                mma16816(d[1][np * 2 + 1], A1, Bf[1], Bf[3]);
            }
        }
    }
}

// A-apply, register-chained: acc[o][n] += Z^T x Abig_k^T (C->A fragments)
__device__ __forceinline__ void apply_chain(float (&acc)[2][4][4],
                                            const float (&d)[2][4][4],
                                            uint32_t sAk, int lane) {
    const uint32_t lrow = (uint32_t)(lane & 15);
    const uint32_t lcol = (uint32_t)((lane >> 4) << 3);
    uint32_t zh2[2][4][2], zl2[2][4][2];
#pragma unroll
    for (int t = 0; t < 2; t++)
#pragma unroll
        for (int j = 0; j < 4; j++)
#pragma unroll
            for (int pr = 0; pr < 2; pr++) {
                float v0 = d[t][j][pr * 2 + 0], v1 = d[t][j][pr * 2 + 1];
                uint32_t zh = pack2(v0, v1);
                __half2 hh = *(__half2*)&zh;
                float2 hf = __half22float2(hh);
                zh2[t][j][pr] = zh;
                zl2[t][j][pr] = pack2(v0 - hf.x, v1 - hf.y);
            }
#pragma unroll
    for (int kh = 0; kh < 2; kh++) {
        uint32_t BH[2][4], BL[2][4];
#pragma unroll
        for (int np = 0; np < 2; np++) {
            ldsm4(BH[np], sAk + ((np * 16 + lrow) * STA + kh * 16 + lcol) * 2);
            ldsm4(BL[np], sAk + ((np * 16 + lrow) * STA + 32 + kh * 16 + lcol) * 2);
        }
#pragma unroll
        for (int t = 0; t < 2; t++) {
            uint32_t Ah_[4] = {zh2[t][2 * kh][0], zh2[t][2 * kh][1],
                               zh2[t][2 * kh + 1][0], zh2[t][2 * kh + 1][1]};
            uint32_t Al_[4] = {zl2[t][2 * kh][0], zl2[t][2 * kh][1],
                               zl2[t][2 * kh + 1][0], zl2[t][2 * kh + 1][1]};
#pragma unroll
            for (int np = 0; np < 2; np++) {
                mma16816(acc[t][np * 2 + 0], Ah_, BH[np][0], BH[np][2]);
                mma16816(acc[t][np * 2 + 1], Ah_, BH[np][1], BH[np][3]);
                mma16816(acc[t][np * 2 + 0], Al_, BH[np][0], BH[np][2]);
                mma16816(acc[t][np * 2 + 1], Al_, BH[np][1], BH[np][3]);
                mma16816(acc[t][np * 2 + 0], Ah_, BL[np][0], BL[np][2]);
                mma16816(acc[t][np * 2 + 1], Ah_, BL[np][1], BL[np][3]);
            }
        }
    }
}

// ------------------------------------------------------------------
__global__ __launch_bounds__(256, 2) void dgcnn_mma_kernel(
    const float* __restrict__ x,
    const float* __restrict__ fcw,
    const float* __restrict__ fcb,
    float* __restrict__ out) {

    extern __shared__ char smem[];
    __half* S = (__half*)smem;
    const uint32_t sb = smem_u32(smem);
    const int tid = threadIdx.x;
    const int w = tid >> 5, lane = tid & 31;
    const int bp = w >> 2, wb = w & 3;       // batch (0..1), o-quarter

    float* sB1 = (float*)(smem + OFF_B1);
    float* sB2 = (float*)(smem + OFF_B2);
    float* sFC = (float*)(smem + OFF_FC);
    float* red = (float*)(smem + OFF_RED);

    // ---- prologue ----
    for (int i = tid; i < 64 * ST1 / 2; i += 256) ((uint32_t*)smem)[i] = 0;
    __syncthreads();
    {
        // X: float4 loads, hi/lo STS.64 (explicit uint2 packing — no &var aliasing)
        const float* xb = x + (size_t)blockIdx.x * 64 * CIN;
        for (int i = tid; i < 64 * 15; i += 256) {
            int row = i / 15, c4 = (i - row * 15) * 4;
            float4 v = *(const float4*)&xb[row * CIN + c4];
            __half h0 = __float2half_rn(v.x), h1 = __float2half_rn(v.y);
            __half h2 = __float2half_rn(v.z), h3 = __float2half_rn(v.w);
            __half2 hA = __halves2half2(h0, h1), hB = __halves2half2(h2, h3);
            uint2 hi; hi.x = *(uint32_t*)&hA; hi.y = *(uint32_t*)&hB;
            *(uint2*)&S[row * ST1 + c4] = hi;
            __half2 lA = __halves2half2(
                __float2half_rn(v.x - __half2float(h0)),
                __float2half_rn(v.y - __half2float(h1)));
            __half2 lB = __halves2half2(
                __float2half_rn(v.z - __half2float(h2)),
                __float2half_rn(v.w - __half2float(h3)));
            uint2 lo; lo.x = *(uint32_t*)&lA; lo.y = *(uint32_t*)&lB;
            *(uint2*)&S[row * ST1 + 64 + c4] = lo;
        }
        for (int i = tid; i < 4096; i += 256) {
            int k = i >> 10, n = (i >> 5) & 31, m = i & 31;
            uint32_t u = g_Ap[k][n][m];
            __half2 p = *(__half2*)&u;
            int base = OFF_A / 2 + (k * 32 + n) * STA;
            S[base + m] = p.x;
            S[base + 32 + m] = p.y;
        }
        for (int i = tid; i < 8192; i += 256) {
            int cc = i >> 12, r = i & 4095;
            int n = r >> 7, o2 = r & 127;
            sFC[(cc * 128 + o2) * 34 + n] = fcw[i];
        }
        if (tid < 128) { sB1[tid] = g_B1[tid]; sB2[tid] = g_B2[tid]; }
    }
    __syncthreads();

    const uint32_t wPanel = sb + OFF_R2 + (wb * 32) * ST1 * 2;
    const uint32_t bXH = sb + OFF_R1 + (bp * 32) * ST1 * 2;

    float acc[2][4][4];
#pragma unroll
    for (int t = 0; t < 2; t++)
#pragma unroll
        for (int j = 0; j < 4; j++)
#pragma unroll
            for (int e = 0; e < 4; e++) acc[t][j][e] = 0.0f;

    // ================= layer 1 =================
    for (int k = 0; k < 4; k++) {
        // stage W1 panel: pure 16B copies
        const float4* src = (const float4*)g_W1s[k];
#pragma unroll
        for (int i = 0; i < 8; i++) {
            int ch = tid * 8 + i;
            int row = ch >> 4, c8 = ch & 15;
            *(float4*)&S[OFF_R2 / 2 + row * ST1 + c8 * 8] = src[ch];
        }
        __syncthreads();
        float d[2][4][4];
        gemm_regs<4, 64, 3>(wPanel, bXH, d, lane);
        if (k == 0) {
#pragma unroll
            for (int t = 0; t < 2; t++)
#pragma unroll
                for (int j = 0; j < 4; j++)
#pragma unroll
                    for (int e = 0; e < 4; e++) acc[t][j][e] += d[t][j][e];
        } else {
            apply_chain(acc, d, sb + OFF_A + k * 32 * STA * 2, lane);
        }
        __syncthreads();
    }

    // H1 = relu(acc + b1) -> R1 hi-only [row][o]
#pragma unroll
    for (int t = 0; t < 2; t++)
#pragma unroll
        for (int j = 0; j < 4; j++)
#pragma unroll
            for (int e = 0; e < 4; e++) {
                int o = wb * 32 + t * 16 + (lane >> 2) + ((e >> 1) << 3);
                int n = j * 8 + ((lane & 3) << 1) + (e & 1);
                float v = fmaxf(acc[t][j][e] + sB1[o], 0.0f);
                S[(bp * 32 + n) * ST1 + o] = __float2half_rn(v);
            }
#pragma unroll
    for (int t = 0; t < 2; t++)
#pragma unroll
        for (int j = 0; j < 4; j++)
#pragma unroll
            for (int e = 0; e < 4; e++) acc[t][j][e] = 0.0f;
    __syncthreads();

    // ================= layer 2 (hi-only GEMM) =================
    for (int k2 = 0; k2 < 4; k2++) {
        const float4* src = (const float4*)g_W2s[k2];
#pragma unroll
        for (int i = 0; i < 8; i++) {
            int ch = tid * 8 + i;
            int row = ch >> 4, c8 = ch & 15;
            *(float4*)&S[OFF_R2 / 2 + row * ST1 + c8 * 8] = src[ch];
        }
        __syncthreads();
        float d[2][4][4];
        gemm_regs<8, 0, 1>(wPanel, bXH, d, lane);
        if (k2 == 0) {
#pragma unroll
            for (int t = 0; t < 2; t++)
#pragma unroll
                for (int j = 0; j < 4; j++)
#pragma unroll
                    for (int e = 0; e < 4; e++) acc[t][j][e] += d[t][j][e];
        } else {
            apply_chain(acc, d, sb + OFF_A + k2 * 32 * STA * 2, lane);
        }
        __syncthreads();
    }

    // ---- FC epilogue ----
    float p0 = 0.0f, p1 = 0.0f;
#pragma unroll
    for (int t = 0; t < 2; t++)
#pragma unroll
        for (int j = 0; j < 4; j++)
#pragma unroll
            for (int e = 0; e < 4; e++) {
                int o2 = wb * 32 + t * 16 + (lane >> 2) + ((e >> 1) << 3);
                int n = j * 8 + ((lane & 3) << 1) + (e & 1);
                float v = fmaxf(acc[t][j][e] + sB2[o2], 0.0f);
                p0 += v * sFC[o2 * 34 + n];
                p1 += v * sFC[(128 + o2) * 34 + n];
            }
#pragma unroll
    for (int off = 16; off > 0; off >>= 1) {
        p0 += __shfl_xor_sync(0xFFFFFFFFu, p0, off);
        p1 += __shfl_xor_sync(0xFFFFFFFFu, p1, off);
    }
    if (lane == 0) { red[w * 2] = p0; red[w * 2 + 1] = p1; }
    __syncthreads();
    if (tid < 4) {
        int b2 = tid >> 1, c = tid & 1;
        float s = red[(b2 * 4 + 0) * 2 + c] + red[(b2 * 4 + 1) * 2 + c] +
                  red[(b2 * 4 + 2) * 2 + c] + red[(b2 * 4 + 3) * 2 + c];
        out[(blockIdx.x * 2 + b2) * 2 + c] = s + fcb[c];
    }
}

// ------------------------------------------------------------------
extern "C" void kernel_launch(void* const* d_in, const int* in_sizes, int n_in,
                              void* d_out, int out_size) {
    const float* x        = (const float*)d_in[0];
    const float* adj      = (const float*)d_in[1];
    const float* adj_bias = (const float*)d_in[2];
    const float* w1       = (const float*)d_in[3];
    const float* b1       = (const float*)d_in[4];
    const float* w2       = (const float*)d_in[5];
    const float* b2       = (const float*)d_in[6];
    const float* fc_w     = (const float*)d_in[7];
    const float* fc_b     = (const float*)d_in[8];
    float* out = (float*)d_out;

    const int B = in_sizes[0] / (NNODE * CIN);

    cudaFuncSetAttribute(dgcnn_mma_kernel,
                         cudaFuncAttributeMaxDynamicSharedMemorySize,
                         SMEM_TOTAL);

    precompute_kernel<<<1, 1024>>>(adj, adj_bias, w1, b1, w2, b2);
    dgcnn_mma_kernel<<<B / 2, 256, SMEM_TOTAL>>>(x, fc_w, fc_b, out);
}

// round 9
// speedup vs baseline: 5.7398x; 1.9853x over previous
#include <cuda_runtime.h>
#include <cuda_fp16.h>
#include <cstdint>

#define NNODE 32
#define CIN   60
#define HID   128
#define KCH   5

// ---- fragment-order packed weights (one LDG.128 per lane per 16x16 tile) ----
// layout [k][otile][ctile][lane][ai]: ai0=(r,c) ai1=(r+8,c) ai2=(r,c+8) ai3=(r+8,c+8)
__device__ __align__(16) uint32_t g_W1fh[4][8][4][32][4];
__device__ __align__(16) uint32_t g_W1fl[4][8][4][32][4];
__device__ __align__(16) uint32_t g_W2fh[4][8][8][32][4];
__device__ uint32_t g_Ap[4][32][32];   // chebyshev matrices, packed hi|lo
__device__ float    g_B1[128];
__device__ float    g_B2[128];

__device__ __forceinline__ uint32_t packhl(float v) {
    __half h = __float2half_rn(v);
    __half l = __float2half_rn(v - __half2float(h));
    return (uint32_t)__half_as_ushort(h) | ((uint32_t)__half_as_ushort(l) << 16);
}
__device__ __forceinline__ uint32_t pack_hh(__half a, __half b) {
    return (uint32_t)__half_as_ushort(a) | ((uint32_t)__half_as_ushort(b) << 16);
}

// ------------------------------------------------------------------
__global__ void precompute_kernel(const float* __restrict__ adj,
                                  const float* __restrict__ adj_bias,
                                  const float* __restrict__ w1,
                                  const float* __restrict__ b1,
                                  const float* __restrict__ w2,
                                  const float* __restrict__ b2) {
    __shared__ float a[NNODE][NNODE];
    __shared__ float L[NNODE][NNODE];
    __shared__ float A3[NNODE][NNODE];
    __shared__ float dre[NNODE];

    int tid = threadIdx.x;
    int n = tid >> 5, m = tid & 31;

    float bias = adj_bias[0];
    a[n][m] = fmaxf(adj[n * NNODE + m] + bias, 0.0f);
    __syncthreads();
    if (m == 0) {
        float s = 0.0f;
        for (int j = 0; j < NNODE; j++) s += a[n][j];
        dre[n] = 1.0f / sqrtf(s + 1e-5f);
    }
    __syncthreads();
    L[n][m] = (n == m ? 1.0f : 0.0f) - dre[n] * a[n][m] * dre[m];
    __syncthreads();
    float s = 0.0f;
    for (int j = 0; j < NNODE; j++) s += L[n][j] * L[j][m];
    A3[n][m] = 2.0f * s - (n == m ? 1.0f : 0.0f);
    __syncthreads();
    float s2 = 0.0f;
    for (int j = 0; j < NNODE; j++) s2 += L[n][j] * A3[j][m];
    float a4 = 2.0f * s2 - L[n][m];

    g_Ap[0][n][m] = packhl(n == m ? 1.0f : 0.0f);
    g_Ap[1][n][m] = packhl(L[n][m]);
    g_Ap[2][n][m] = packhl(A3[n][m]);
    g_Ap[3][n][m] = packhl(a4);

    // W1 fragments hi + lo: row=o, col=c (zero pad c>=60)
    for (int idx = tid; idx < 4 * 8 * 4 * 32; idx += blockDim.x) {
        int lane = idx & 31;
        int ct = (idx >> 5) & 3;
        int ot = (idx >> 7) & 7;
        int k = idx >> 10;
        int r0 = lane >> 2, cp = (lane & 3) * 2;
        for (int ai = 0; ai < 4; ai++) {
            int row = ot * 16 + r0 + (ai & 1) * 8;
            int col = ct * 16 + cp + (ai >> 1) * 8;
            float v0 = (col < CIN) ? w1[(col * KCH + k + 1) * HID + row] : 0.0f;
            float v1 = (col + 1 < CIN) ? w1[((col + 1) * KCH + k + 1) * HID + row] : 0.0f;
            __half h0 = __float2half_rn(v0), h1 = __float2half_rn(v1);
            g_W1fh[k][ot][ct][lane][ai] = pack_hh(h0, h1);
            g_W1fl[k][ot][ct][lane][ai] =
                pack_hh(__float2half_rn(v0 - __half2float(h0)),
                        __float2half_rn(v1 - __half2float(h1)));
        }
    }
    // W2 fragments hi only: row=o2, col=o
    for (int idx = tid; idx < 4 * 8 * 8 * 32; idx += blockDim.x) {
        int lane = idx & 31;
        int ct = (idx >> 5) & 7;
        int ot = (idx >> 8) & 7;
        int k = idx >> 11;
        int r0 = lane >> 2, cp = (lane & 3) * 2;
        for (int ai = 0; ai < 4; ai++) {
            int row = ot * 16 + r0 + (ai & 1) * 8;
            int col = ct * 16 + cp + (ai >> 1) * 8;
            float v0 = w2[(col * KCH + k + 1) * HID + row];
            float v1 = w2[((col + 1) * KCH + k + 1) * HID + row];
            g_W2fh[k][ot][ct][lane][ai] =
                pack_hh(__float2half_rn(v0), __float2half_rn(v1));
        }
    }
    if (tid < HID) {
        float s1 = b1[tid];
        for (int c = 0; c < CIN; c++) s1 += w1[(c * KCH) * HID + tid];
        g_B1[tid] = s1;
        float sb = b2[tid];
        for (int c = 0; c < HID; c++) sb += w2[(c * KCH) * HID + tid];
        g_B2[tid] = sb;
    }
}

// ------------------------------------------------------------------
__device__ __forceinline__ uint32_t smem_u32(const void* p) {
    uint32_t a;
    asm("{ .reg .u64 t; cvta.to.shared.u64 t, %1; cvt.u32.u64 %0, t; }"
        : "=r"(a) : "l"(p));
    return a;
}
__device__ __forceinline__ void ldsm4(uint32_t* r, uint32_t addr) {
    asm volatile("ldmatrix.sync.aligned.m8n8.x4.shared.b16 {%0,%1,%2,%3}, [%4];\n"
                 : "=r"(r[0]), "=r"(r[1]), "=r"(r[2]), "=r"(r[3]) : "r"(addr));
}
__device__ __forceinline__ void mma16816(float* d, const uint32_t* a,
                                         uint32_t b0, uint32_t b1) {
    asm volatile(
        "mma.sync.aligned.m16n8k16.row.col.f32.f16.f16.f32 "
        "{%0,%1,%2,%3},{%4,%5,%6,%7},{%8,%9},{%0,%1,%2,%3};\n"
        : "+f"(d[0]), "+f"(d[1]), "+f"(d[2]), "+f"(d[3])
        : "r"(a[0]), "r"(a[1]), "r"(a[2]), "r"(a[3]), "r"(b0), "r"(b1));
}
__device__ __forceinline__ uint32_t pack2(float x, float y) {
    __half2 h = __float22half2_rn(make_float2(x, y));
    return *(uint32_t*)&h;
}

// ---- smem strides (halfs) ----
#define ST1 136   // rows: layer1 X [hi 0..63|lo 64..127|pad]; layer2 H [hi 0..127|pad]
#define STA 72    // A: [n][Ah 0..31 | Al 32..63 | pad]

// ---- smem regions (bytes) ----
#define OFF_R1  0        // [64][ST1]  X (l1) / H (l2)   17408
#define OFF_A   17408    // [4][32][STA]                 18432
#define OFF_B1  35840
#define OFF_B2  36352
#define OFF_FC  36864    // [2][128][34] f32             34816
#define OFF_RED 71680
#define SMEM_TOTAL 71808

// A-apply, register-chained: acc[o][n] += Z^T x Abig_k^T (C->A fragments)
__device__ __forceinline__ void apply_chain(float (&acc)[2][4][4],
                                            const float (&d)[2][4][4],
                                            uint32_t sAk, int lane) {
    const uint32_t lrow = (uint32_t)(lane & 15);
    const uint32_t lcol = (uint32_t)((lane >> 4) << 3);
    uint32_t zh2[2][4][2], zl2[2][4][2];
#pragma unroll
    for (int t = 0; t < 2; t++)
#pragma unroll
        for (int j = 0; j < 4; j++)
#pragma unroll
            for (int pr = 0; pr < 2; pr++) {
                float v0 = d[t][j][pr * 2 + 0], v1 = d[t][j][pr * 2 + 1];
                uint32_t zh = pack2(v0, v1);
                __half2 hh = *(__half2*)&zh;
                float2 hf = __half22float2(hh);
                zh2[t][j][pr] = zh;
                zl2[t][j][pr] = pack2(v0 - hf.x, v1 - hf.y);
            }
#pragma unroll
    for (int kh = 0; kh < 2; kh++) {
        uint32_t BH[2][4], BL[2][4];
#pragma unroll
        for (int np = 0; np < 2; np++) {
            ldsm4(BH[np], sAk + ((np * 16 + lrow) * STA + kh * 16 + lcol) * 2);
            ldsm4(BL[np], sAk + ((np * 16 + lrow) * STA + 32 + kh * 16 + lcol) * 2);
        }
#pragma unroll
        for (int t = 0; t < 2; t++) {
            uint32_t Ah_[4] = {zh2[t][2 * kh][0], zh2[t][2 * kh][1],
                               zh2[t][2 * kh + 1][0], zh2[t][2 * kh + 1][1]};
            uint32_t Al_[4] = {zl2[t][2 * kh][0], zl2[t][2 * kh][1],
                               zl2[t][2 * kh + 1][0], zl2[t][2 * kh + 1][1]};
#pragma unroll
            for (int np = 0; np < 2; np++) {
                mma16816(acc[t][np * 2 + 0], Ah_, BH[np][0], BH[np][2]);
                mma16816(acc[t][np * 2 + 1], Ah_, BH[np][1], BH[np][3]);
                mma16816(acc[t][np * 2 + 0], Al_, BH[np][0], BH[np][2]);
                mma16816(acc[t][np * 2 + 1], Al_, BH[np][1], BH[np][3]);
                mma16816(acc[t][np * 2 + 0], Ah_, BL[np][0], BL[np][2]);
                mma16816(acc[t][np * 2 + 1], Ah_, BL[np][1], BL[np][3]);
            }
        }
    }
}

// ------------------------------------------------------------------
__global__ __launch_bounds__(256, 2) void dgcnn_mma_kernel(
    const float* __restrict__ x,
    const float* __restrict__ fcw,
    const float* __restrict__ fcb,
    float* __restrict__ out) {

    extern __shared__ char smem[];
    __half* S = (__half*)smem;
    const uint32_t sb = smem_u32(smem);
    const int tid = threadIdx.x;
    const int w = tid >> 5, lane = tid & 31;
    const int bp = w >> 2, wb = w & 3;       // batch (0..1), o-quarter

    float* sB1 = (float*)(smem + OFF_B1);
    float* sB2 = (float*)(smem + OFF_B2);
    float* sFC = (float*)(smem + OFF_FC);
    float* red = (float*)(smem + OFF_RED);

    // ---- prologue ----
    for (int i = tid; i < 64 * ST1 / 2; i += 256) ((uint32_t*)smem)[i] = 0;
    __syncthreads();
    {
        const float* xb = x + (size_t)blockIdx.x * 64 * CIN;
        for (int i = tid; i < 64 * 15; i += 256) {
            int row = i / 15, c4 = (i - row * 15) * 4;
            float4 v = *(const float4*)&xb[row * CIN + c4];
            __half h0 = __float2half_rn(v.x), h1 = __float2half_rn(v.y);
            __half h2 = __float2half_rn(v.z), h3 = __float2half_rn(v.w);
            uint2 hi;
            hi.x = pack_hh(h0, h1);
            hi.y = pack_hh(h2, h3);
            *(uint2*)&S[row * ST1 + c4] = hi;
            uint2 lo;
            lo.x = pack_hh(__float2half_rn(v.x - __half2float(h0)),
                           __float2half_rn(v.y - __half2float(h1)));
            lo.y = pack_hh(__float2half_rn(v.z - __half2float(h2)),
                           __float2half_rn(v.w - __half2float(h3)));
            *(uint2*)&S[row * ST1 + 64 + c4] = lo;
        }
        for (int i = tid; i < 4096; i += 256) {
            int k = i >> 10, n = (i >> 5) & 31, m = i & 31;
            uint32_t u = g_Ap[k][n][m];
            __half2 p = *(__half2*)&u;
            int base = OFF_A / 2 + (k * 32 + n) * STA;
            S[base + m] = p.x;
            S[base + 32 + m] = p.y;
        }
        for (int i = tid; i < 8192; i += 256) {
            int cc = i >> 12, r = i & 4095;
            int n = r >> 7, o2 = r & 127;
            sFC[(cc * 128 + o2) * 34 + n] = fcw[i];
        }
        if (tid < 128) { sB1[tid] = g_B1[tid]; sB2[tid] = g_B2[tid]; }
    }
    __syncthreads();

    const uint32_t bXH = sb + OFF_R1 + (bp * 32) * ST1 * 2;
    const uint32_t lrow = (uint32_t)(lane & 15);
    const uint32_t lcol = (uint32_t)((lane >> 4) << 3);

    float acc[2][4][4];
#pragma unroll
    for (int t = 0; t < 2; t++)
#pragma unroll
        for (int j = 0; j < 4; j++)
#pragma unroll
            for (int e = 0; e < 4; e++) acc[t][j][e] = 0.0f;

    // ================= layer 1 (no barriers in loop) =================
    for (int k = 0; k < 4; k++) {
        float d[2][4][4];
#pragma unroll
        for (int t = 0; t < 2; t++)
#pragma unroll
            for (int j = 0; j < 4; j++)
#pragma unroll
                for (int e = 0; e < 4; e++) d[t][j][e] = 0.0f;

#pragma unroll
        for (int c = 0; c < 4; c++) {
            uint4 ah0 = *(const uint4*)g_W1fh[k][wb * 2 + 0][c][lane];
            uint4 ah1 = *(const uint4*)g_W1fh[k][wb * 2 + 1][c][lane];
            uint4 al0 = *(const uint4*)g_W1fl[k][wb * 2 + 0][c][lane];
            uint4 al1 = *(const uint4*)g_W1fl[k][wb * 2 + 1][c][lane];
            uint32_t Ah0[4] = {ah0.x, ah0.y, ah0.z, ah0.w};
            uint32_t Ah1[4] = {ah1.x, ah1.y, ah1.z, ah1.w};
            uint32_t Al0[4] = {al0.x, al0.y, al0.z, al0.w};
            uint32_t Al1[4] = {al1.x, al1.y, al1.z, al1.w};
            uint32_t Bh[2][4], Bl[2][4];
#pragma unroll
            for (int np = 0; np < 2; np++) {
                ldsm4(Bh[np], bXH + ((np * 16 + lrow) * ST1 + c * 16 + lcol) * 2);
                ldsm4(Bl[np], bXH + ((np * 16 + lrow) * ST1 + 64 + c * 16 + lcol) * 2);
            }
#pragma unroll
            for (int np = 0; np < 2; np++) {
                mma16816(d[0][np * 2 + 0], Ah0, Bh[np][0], Bh[np][2]);
                mma16816(d[0][np * 2 + 1], Ah0, Bh[np][1], Bh[np][3]);
                mma16816(d[1][np * 2 + 0], Ah1, Bh[np][0], Bh[np][2]);
                mma16816(d[1][np * 2 + 1], Ah1, Bh[np][1], Bh[np][3]);
                mma16816(d[0][np * 2 + 0], Al0, Bh[np][0], Bh[np][2]);
                mma16816(d[0][np * 2 + 1], Al0, Bh[np][1], Bh[np][3]);
                mma16816(d[1][np * 2 + 0], Al1, Bh[np][0], Bh[np][2]);
                mma16816(d[1][np * 2 + 1], Al1, Bh[np][1], Bh[np][3]);
                mma16816(d[0][np * 2 + 0], Ah0, Bl[np][0], Bl[np][2]);
                mma16816(d[0][np * 2 + 1], Ah0, Bl[np][1], Bl[np][3]);
                mma16816(d[1][np * 2 + 0], Ah1, Bl[np][0], Bl[np][2]);
                mma16816(d[1][np * 2 + 1], Ah1, Bl[np][1], Bl[np][3]);
            }
        }
        if (k == 0) {
#pragma unroll
            for (int t = 0; t < 2; t++)
#pragma unroll
                for (int j = 0; j < 4; j++)
#pragma unroll
                    for (int e = 0; e < 4; e++) acc[t][j][e] += d[t][j][e];
        } else {
            apply_chain(acc, d, sb + OFF_A + k * 32 * STA * 2, lane);
        }
    }

    // H1 = relu(acc + b1) -> R1 hi-only [row][o]  (barrier both sides)
    __syncthreads();
#pragma unroll
    for (int t = 0; t < 2; t++)
#pragma unroll
        for (int j = 0; j < 4; j++)
#pragma unroll
            for (int e = 0; e < 4; e++) {
                int o = wb * 32 + t * 16 + (lane >> 2) + ((e >> 1) << 3);
                int n = j * 8 + ((lane & 3) << 1) + (e & 1);
                float v = fmaxf(acc[t][j][e] + sB1[o], 0.0f);
                S[(bp * 32 + n) * ST1 + o] = __float2half_rn(v);
            }
#pragma unroll
    for (int t = 0; t < 2; t++)
#pragma unroll
        for (int j = 0; j < 4; j++)
#pragma unroll
            for (int e = 0; e < 4; e++) acc[t][j][e] = 0.0f;
    __syncthreads();

    // ================= layer 2 (hi-only, no barriers in loop) =================
    for (int k2 = 0; k2 < 4; k2++) {
        float d[2][4][4];
#pragma unroll
        for (int t = 0; t < 2; t++)
#pragma unroll
            for (int j = 0; j < 4; j++)
#pragma unroll
                for (int e = 0; e < 4; e++) d[t][j][e] = 0.0f;

#pragma unroll
        for (int c = 0; c < 8; c++) {
            uint4 ah0 = *(const uint4*)g_W2fh[k2][wb * 2 + 0][c][lane];
            uint4 ah1 = *(const uint4*)g_W2fh[k2][wb * 2 + 1][c][lane];
            uint32_t Ah0[4] = {ah0.x, ah0.y, ah0.z, ah0.w};
            uint32_t Ah1[4] = {ah1.x, ah1.y, ah1.z, ah1.w};
#pragma unroll
            for (int np = 0; np < 2; np++) {
                uint32_t Bf[4];
                ldsm4(Bf, bXH + ((np * 16 + lrow) * ST1 + c * 16 + lcol) * 2);
                mma16816(d[0][np * 2 + 0], Ah0, Bf[0], Bf[2]);
                mma16816(d[0][np * 2 + 1], Ah0, Bf[1], Bf[3]);
                mma16816(d[1][np * 2 + 0], Ah1, Bf[0], Bf[2]);
                mma16816(d[1][np * 2 + 1], Ah1, Bf[1], Bf[3]);
            }
        }
        if (k2 == 0) {
#pragma unroll
            for (int t = 0; t < 2; t++)
#pragma unroll
                for (int j = 0; j < 4; j++)
#pragma unroll
                    for (int e = 0; e < 4; e++) acc[t][j][e] += d[t][j][e];
        } else {
            apply_chain(acc, d, sb + OFF_A + k2 * 32 * STA * 2, lane);
        }
    }

    // ---- FC epilogue ----
    float p0 = 0.0f, p1 = 0.0f;
#pragma unroll
    for (int t = 0; t < 2; t++)
#pragma unroll
        for (int j = 0; j < 4; j++)
#pragma unroll
            for (int e = 0; e < 4; e++) {
                int o2 = wb * 32 + t * 16 + (lane >> 2) + ((e >> 1) << 3);
                int n = j * 8 + ((lane & 3) << 1) + (e & 1);
                float v = fmaxf(acc[t][j][e] + sB2[o2], 0.0f);
                p0 += v * sFC[o2 * 34 + n];
                p1 += v * sFC[(128 + o2) * 34 + n];
            }
#pragma unroll
    for (int off = 16; off > 0; off >>= 1) {
        p0 += __shfl_xor_sync(0xFFFFFFFFu, p0, off);
        p1 += __shfl_xor_sync(0xFFFFFFFFu, p1, off);
    }
    if (lane == 0) { red[w * 2] = p0; red[w * 2 + 1] = p1; }
    __syncthreads();
    if (tid < 4) {
        int b2 = tid >> 1, c = tid & 1;
        float s = red[(b2 * 4 + 0) * 2 + c] + red[(b2 * 4 + 1) * 2 + c] +
                  red[(b2 * 4 + 2) * 2 + c] + red[(b2 * 4 + 3) * 2 + c];
        out[(blockIdx.x * 2 + b2) * 2 + c] = s + fcb[c];
    }
}

// ------------------------------------------------------------------
extern "C" void kernel_launch(void* const* d_in, const int* in_sizes, int n_in,
                              void* d_out, int out_size) {
    const float* x        = (const float*)d_in[0];
    const float* adj      = (const float*)d_in[1];
    const float* adj_bias = (const float*)d_in[2];
    const float* w1       = (const float*)d_in[3];
    const float* b1       = (const float*)d_in[4];
    const float* w2       = (const float*)d_in[5];
    const float* b2       = (const float*)d_in[6];
    const float* fc_w     = (const float*)d_in[7];
    const float* fc_b     = (const float*)d_in[8];
    float* out = (float*)d_out;

    const int B = in_sizes[0] / (NNODE * CIN);

    cudaFuncSetAttribute(dgcnn_mma_kernel,
                         cudaFuncAttributeMaxDynamicSharedMemorySize,
                         SMEM_TOTAL);

    precompute_kernel<<<1, 1024>>>(adj, adj_bias, w1, b1, w2, b2);
    dgcnn_mma_kernel<<<B / 2, 256, SMEM_TOTAL>>>(x, fc_w, fc_b, out);
}

// round 10
// speedup vs baseline: 6.9138x; 1.2045x over previous
#include <cuda_runtime.h>
#include <cuda_fp16.h>
#include <cstdint>

#define NNODE 32
#define CIN   60
#define HID   128
#define KCH   5

// ---- fragment-order packed weights (one LDG.128 per lane per 16x16 tile) ----
__device__ __align__(16) uint32_t g_W1fh[4][8][4][32][4];
__device__ __align__(16) uint32_t g_W1fl[4][8][4][32][4];
__device__ __align__(16) uint32_t g_W2fh[4][8][8][32][4];
__device__ uint32_t g_Ap[4][32][32];   // chebyshev matrices, packed hi|lo
__device__ float    g_B1[128];
__device__ float    g_B2[128];

__device__ __forceinline__ uint32_t packhl(float v) {
    __half h = __float2half_rn(v);
    __half l = __float2half_rn(v - __half2float(h));
    return (uint32_t)__half_as_ushort(h) | ((uint32_t)__half_as_ushort(l) << 16);
}
__device__ __forceinline__ uint32_t pack_hh(__half a, __half b) {
    return (uint32_t)__half_as_ushort(a) | ((uint32_t)__half_as_ushort(b) << 16);
}

// ------------------------------------------------------------------
__global__ void precompute_kernel(const float* __restrict__ adj,
                                  const float* __restrict__ adj_bias,
                                  const float* __restrict__ w1,
                                  const float* __restrict__ b1,
                                  const float* __restrict__ w2,
                                  const float* __restrict__ b2) {
    __shared__ float a[NNODE][NNODE];
    __shared__ float L[NNODE][NNODE];
    __shared__ float A3[NNODE][NNODE];
    __shared__ float dre[NNODE];

    int tid = threadIdx.x;
    int n = tid >> 5, m = tid & 31;

    float bias = adj_bias[0];
    a[n][m] = fmaxf(adj[n * NNODE + m] + bias, 0.0f);
    __syncthreads();
    if (m == 0) {
        float s = 0.0f;
        for (int j = 0; j < NNODE; j++) s += a[n][j];
        dre[n] = 1.0f / sqrtf(s + 1e-5f);
    }
    __syncthreads();
    L[n][m] = (n == m ? 1.0f : 0.0f) - dre[n] * a[n][m] * dre[m];
    __syncthreads();
    float s = 0.0f;
    for (int j = 0; j < NNODE; j++) s += L[n][j] * L[j][m];
    A3[n][m] = 2.0f * s - (n == m ? 1.0f : 0.0f);
    __syncthreads();
    float s2 = 0.0f;
    for (int j = 0; j < NNODE; j++) s2 += L[n][j] * A3[j][m];
    float a4 = 2.0f * s2 - L[n][m];

    g_Ap[0][n][m] = packhl(n == m ? 1.0f : 0.0f);
    g_Ap[1][n][m] = packhl(L[n][m]);
    g_Ap[2][n][m] = packhl(A3[n][m]);
    g_Ap[3][n][m] = packhl(a4);

    // W1 fragments hi + lo: row=o, col=c (zero pad c>=60)
    for (int idx = tid; idx < 4 * 8 * 4 * 32; idx += blockDim.x) {
        int lane = idx & 31;
        int ct = (idx >> 5) & 3;
        int ot = (idx >> 7) & 7;
        int k = idx >> 10;
        int r0 = lane >> 2, cp = (lane & 3) * 2;
        for (int ai = 0; ai < 4; ai++) {
            int row = ot * 16 + r0 + (ai & 1) * 8;
            int col = ct * 16 + cp + (ai >> 1) * 8;
            float v0 = (col < CIN) ? w1[(col * KCH + k + 1) * HID + row] : 0.0f;
            float v1 = (col + 1 < CIN) ? w1[((col + 1) * KCH + k + 1) * HID + row] : 0.0f;
            __half h0 = __float2half_rn(v0), h1 = __float2half_rn(v1);
            g_W1fh[k][ot][ct][lane][ai] = pack_hh(h0, h1);
            g_W1fl[k][ot][ct][lane][ai] =
                pack_hh(__float2half_rn(v0 - __half2float(h0)),
                        __float2half_rn(v1 - __half2float(h1)));
        }
    }
    // W2 fragments hi only: row=o2, col=o
    for (int idx = tid; idx < 4 * 8 * 8 * 32; idx += blockDim.x) {
        int lane = idx & 31;
        int ct = (idx >> 5) & 7;
        int ot = (idx >> 8) & 7;
        int k = idx >> 11;
        int r0 = lane >> 2, cp = (lane & 3) * 2;
        for (int ai = 0; ai < 4; ai++) {
            int row = ot * 16 + r0 + (ai & 1) * 8;
            int col = ct * 16 + cp + (ai >> 1) * 8;
            float v0 = w2[(col * KCH + k + 1) * HID + row];
            float v1 = w2[((col + 1) * KCH + k + 1) * HID + row];
            g_W2fh[k][ot][ct][lane][ai] =
                pack_hh(__float2half_rn(v0), __float2half_rn(v1));
        }
    }
    if (tid < HID) {
        float s1 = b1[tid];
        for (int c = 0; c < CIN; c++) s1 += w1[(c * KCH) * HID + tid];
        g_B1[tid] = s1;
        float sb = b2[tid];
        for (int c = 0; c < HID; c++) sb += w2[(c * KCH) * HID + tid];
        g_B2[tid] = sb;
    }
}

// ------------------------------------------------------------------
__device__ __forceinline__ uint32_t smem_u32(const void* p) {
    uint32_t a;
    asm("{ .reg .u64 t; cvta.to.shared.u64 t, %1; cvt.u32.u64 %0, t; }"
        : "=r"(a) : "l"(p));
    return a;
}
__device__ __forceinline__ void ldsm4(uint32_t* r, uint32_t addr) {
    asm volatile("ldmatrix.sync.aligned.m8n8.x4.shared.b16 {%0,%1,%2,%3}, [%4];\n"
                 : "=r"(r[0]), "=r"(r[1]), "=r"(r[2]), "=r"(r[3]) : "r"(addr));
}
__device__ __forceinline__ void mma16816(float* d, const uint32_t* a,
                                         uint32_t b0, uint32_t b1) {
    asm volatile(
        "mma.sync.aligned.m16n8k16.row.col.f32.f16.f16.f32 "
        "{%0,%1,%2,%3},{%4,%5,%6,%7},{%8,%9},{%0,%1,%2,%3};\n"
        : "+f"(d[0]), "+f"(d[1]), "+f"(d[2]), "+f"(d[3])
        : "r"(a[0]), "r"(a[1]), "r"(a[2]), "r"(a[3]), "r"(b0), "r"(b1));
}
__device__ __forceinline__ uint32_t pack2(float x, float y) {
    __half2 h = __float22half2_rn(make_float2(x, y));
    return *(uint32_t*)&h;
}

// ---- smem strides (halfs) ----
#define STX 72    // layer1 X rows: [hi 0..63 | pad]
#define STH 136   // layer2 H rows: [hi 0..127 | pad]
#define STA 72    // A: [n][Ah 0..31 | Al 32..63 | pad]

// ---- smem regions (bytes) ----
#define OFF_R1  0        // [64][STH]  X (l1, stride STX) / H (l2, stride STH)
#define OFF_A   17408    // [4][32][STA]                 18432
#define OFF_B1  35840
#define OFF_B2  36352
#define OFF_FC  36864    // [2][128][34] f32             34816
#define OFF_RED 71680
#define SMEM_TOTAL 71808

// A-apply, register-chained, 2-pass: acc += Zh x (Ah + Al)
__device__ __forceinline__ void apply_chain(float (&acc)[2][4][4],
                                            const float (&d)[2][4][4],
                                            uint32_t sAk, int lane) {
    const uint32_t lrow = (uint32_t)(lane & 15);
    const uint32_t lcol = (uint32_t)((lane >> 4) << 3);
    uint32_t zh2[2][4][2];
#pragma unroll
    for (int t = 0; t < 2; t++)
#pragma unroll
        for (int j = 0; j < 4; j++)
#pragma unroll
            for (int pr = 0; pr < 2; pr++)
                zh2[t][j][pr] = pack2(d[t][j][pr * 2 + 0], d[t][j][pr * 2 + 1]);
#pragma unroll
    for (int kh = 0; kh < 2; kh++) {
        uint32_t BH[2][4], BL[2][4];
#pragma unroll
        for (int np = 0; np < 2; np++) {
            ldsm4(BH[np], sAk + ((np * 16 + lrow) * STA + kh * 16 + lcol) * 2);
            ldsm4(BL[np], sAk + ((np * 16 + lrow) * STA + 32 + kh * 16 + lcol) * 2);
        }
#pragma unroll
        for (int t = 0; t < 2; t++) {
            uint32_t Ah_[4] = {zh2[t][2 * kh][0], zh2[t][2 * kh][1],
                               zh2[t][2 * kh + 1][0], zh2[t][2 * kh + 1][1]};
#pragma unroll
            for (int np = 0; np < 2; np++) {
                mma16816(acc[t][np * 2 + 0], Ah_, BH[np][0], BH[np][2]);
                mma16816(acc[t][np * 2 + 1], Ah_, BH[np][1], BH[np][3]);
                mma16816(acc[t][np * 2 + 0], Ah_, BL[np][0], BL[np][2]);
                mma16816(acc[t][np * 2 + 1], Ah_, BL[np][1], BL[np][3]);
            }
        }
    }
}

// ------------------------------------------------------------------
__global__ __launch_bounds__(256, 2) void dgcnn_mma_kernel(
    const float* __restrict__ x,
    const float* __restrict__ fcw,
    const float* __restrict__ fcb,
    float* __restrict__ out) {

    extern __shared__ char smem[];
    __half* S = (__half*)smem;
    const uint32_t sb = smem_u32(smem);
    const int tid = threadIdx.x;
    const int w = tid >> 5, lane = tid & 31;
    const int bp = w >> 2, wb = w & 3;       // batch (0..1), o-quarter

    float* sB1 = (float*)(smem + OFF_B1);
    float* sB2 = (float*)(smem + OFF_B2);
    float* sFC = (float*)(smem + OFF_FC);
    float* red = (float*)(smem + OFF_RED);

    // ---- prologue ----
    for (int i = tid; i < 64 * STH / 2; i += 256) ((uint32_t*)smem)[i] = 0;
    __syncthreads();
    {
        // X hi-only staging
        const float* xb = x + (size_t)blockIdx.x * 64 * CIN;
        for (int i = tid; i < 64 * 15; i += 256) {
            int row = i / 15, c4 = (i - row * 15) * 4;
            float4 v = *(const float4*)&xb[row * CIN + c4];
            uint2 hi;
            hi.x = pack_hh(__float2half_rn(v.x), __float2half_rn(v.y));
            hi.y = pack_hh(__float2half_rn(v.z), __float2half_rn(v.w));
            *(uint2*)&S[row * STX + c4] = hi;
        }
        for (int i = tid; i < 4096; i += 256) {
            int k = i >> 10, n = (i >> 5) & 31, m = i & 31;
            uint32_t u = g_Ap[k][n][m];
            __half2 p = *(__half2*)&u;
            int base = OFF_A / 2 + (k * 32 + n) * STA;
            S[base + m] = p.x;
            S[base + 32 + m] = p.y;
        }
        for (int i = tid; i < 8192; i += 256) {
            int cc = i >> 12, r = i & 4095;
            int n = r >> 7, o2 = r & 127;
            sFC[(cc * 128 + o2) * 34 + n] = fcw[i];
        }
        if (tid < 128) { sB1[tid] = g_B1[tid]; sB2[tid] = g_B2[tid]; }
    }
    __syncthreads();

    const uint32_t bX = sb + OFF_R1 + (bp * 32) * STX * 2;
    const uint32_t bH = sb + OFF_R1 + (bp * 32) * STH * 2;
    const uint32_t lrow = (uint32_t)(lane & 15);
    const uint32_t lcol = (uint32_t)((lane >> 4) << 3);

    float acc[2][4][4];
#pragma unroll
    for (int t = 0; t < 2; t++)
#pragma unroll
        for (int j = 0; j < 4; j++)
#pragma unroll
            for (int e = 0; e < 4; e++) acc[t][j][e] = 0.0f;

    // ================= layer 1 (2-pass: Wh*Xh + Wl*Xh) =================
    for (int k = 0; k < 4; k++) {
        float d[2][4][4];
#pragma unroll
        for (int t = 0; t < 2; t++)
#pragma unroll
            for (int j = 0; j < 4; j++)
#pragma unroll
                for (int e = 0; e < 4; e++) d[t][j][e] = 0.0f;

#pragma unroll
        for (int c = 0; c < 4; c++) {
            uint4 ah0 = *(const uint4*)g_W1fh[k][wb * 2 + 0][c][lane];
            uint4 ah1 = *(const uint4*)g_W1fh[k][wb * 2 + 1][c][lane];
            uint4 al0 = *(const uint4*)g_W1fl[k][wb * 2 + 0][c][lane];
            uint4 al1 = *(const uint4*)g_W1fl[k][wb * 2 + 1][c][lane];
            uint32_t Ah0[4] = {ah0.x, ah0.y, ah0.z, ah0.w};
            uint32_t Ah1[4] = {ah1.x, ah1.y, ah1.z, ah1.w};
            uint32_t Al0[4] = {al0.x, al0.y, al0.z, al0.w};
            uint32_t Al1[4] = {al1.x, al1.y, al1.z, al1.w};
            uint32_t Bh[2][4];
#pragma unroll
            for (int np = 0; np < 2; np++)
                ldsm4(Bh[np], bX + ((np * 16 + lrow) * STX + c * 16 + lcol) * 2);
#pragma unroll
            for (int np = 0; np < 2; np++) {
                mma16816(d[0][np * 2 + 0], Ah0, Bh[np][0], Bh[np][2]);
                mma16816(d[0][np * 2 + 1], Ah0, Bh[np][1], Bh[np][3]);
                mma16816(d[1][np * 2 + 0], Ah1, Bh[np][0], Bh[np][2]);
                mma16816(d[1][np * 2 + 1], Ah1, Bh[np][1], Bh[np][3]);
                mma16816(d[0][np * 2 + 0], Al0, Bh[np][0], Bh[np][2]);
                mma16816(d[0][np * 2 + 1], Al0, Bh[np][1], Bh[np][3]);
                mma16816(d[1][np * 2 + 0], Al1, Bh[np][0], Bh[np][2]);
                mma16816(d[1][np * 2 + 1], Al1, Bh[np][1], Bh[np][3]);
            }
        }
        if (k == 0) {
#pragma unroll
            for (int t = 0; t < 2; t++)
#pragma unroll
                for (int j = 0; j < 4; j++)
#pragma unroll
                    for (int e = 0; e < 4; e++) acc[t][j][e] += d[t][j][e];
        } else {
            apply_chain(acc, d, sb + OFF_A + k * 32 * STA * 2, lane);
        }
    }

    // H1 = relu(acc + b1) -> R1 hi-only [row][o], stride STH
    __syncthreads();
#pragma unroll
    for (int t = 0; t < 2; t++)
#pragma unroll
        for (int j = 0; j < 4; j++)
#pragma unroll
            for (int e = 0; e < 4; e++) {
                int o = wb * 32 + t * 16 + (lane >> 2) + ((e >> 1) << 3);
                int n = j * 8 + ((lane & 3) << 1) + (e & 1);
                float v = fmaxf(acc[t][j][e] + sB1[o], 0.0f);
                S[(bp * 32 + n) * STH + o] = __float2half_rn(v);
            }
#pragma unroll
    for (int t = 0; t < 2; t++)
#pragma unroll
        for (int j = 0; j < 4; j++)
#pragma unroll
            for (int e = 0; e < 4; e++) acc[t][j][e] = 0.0f;
    __syncthreads();

    // ================= layer 2 (hi-only) =================
    for (int k2 = 0; k2 < 4; k2++) {
        float d[2][4][4];
#pragma unroll
        for (int t = 0; t < 2; t++)
#pragma unroll
            for (int j = 0; j < 4; j++)
#pragma unroll
                for (int e = 0; e < 4; e++) d[t][j][e] = 0.0f;

#pragma unroll
        for (int c = 0; c < 8; c++) {
            uint4 ah0 = *(const uint4*)g_W2fh[k2][wb * 2 + 0][c][lane];
            uint4 ah1 = *(const uint4*)g_W2fh[k2][wb * 2 + 1][c][lane];
            uint32_t Ah0[4] = {ah0.x, ah0.y, ah0.z, ah0.w};
            uint32_t Ah1[4] = {ah1.x, ah1.y, ah1.z, ah1.w};
#pragma unroll
            for (int np = 0; np < 2; np++) {
                uint32_t Bf[4];
                ldsm4(Bf, bH + ((np * 16 + lrow) * STH + c * 16 + lcol) * 2);
                mma16816(d[0][np * 2 + 0], Ah0, Bf[0], Bf[2]);
                mma16816(d[0][np * 2 + 1], Ah0, Bf[1], Bf[3]);
                mma16816(d[1][np * 2 + 0], Ah1, Bf[0], Bf[2]);
                mma16816(d[1][np * 2 + 1], Ah1, Bf[1], Bf[3]);
            }
        }
        if (k2 == 0) {
#pragma unroll
            for (int t = 0; t < 2; t++)
#pragma unroll
                for (int j = 0; j < 4; j++)
#pragma unroll
                    for (int e = 0; e < 4; e++) acc[t][j][e] += d[t][j][e];
        } else {
            apply_chain(acc, d, sb + OFF_A + k2 * 32 * STA * 2, lane);
        }
    }

    // ---- FC epilogue ----
    float p0 = 0.0f, p1 = 0.0f;
#pragma unroll
    for (int t = 0; t < 2; t++)
#pragma unroll
        for (int j = 0; j < 4; j++)
#pragma unroll
            for (int e = 0; e < 4; e++) {
                int o2 = wb * 32 + t * 16 + (lane >> 2) + ((e >> 1) << 3);
                int n = j * 8 + ((lane & 3) << 1) + (e & 1);
                float v = fmaxf(acc[t][j][e] + sB2[o2], 0.0f);
                p0 += v * sFC[o2 * 34 + n];
                p1 += v * sFC[(128 + o2) * 34 + n];
            }
#pragma unroll
    for (int off = 16; off > 0; off >>= 1) {
        p0 += __shfl_xor_sync(0xFFFFFFFFu, p0, off);
        p1 += __shfl_xor_sync(0xFFFFFFFFu, p1, off);
    }
    if (lane == 0) { red[w * 2] = p0; red[w * 2 + 1] = p1; }
    __syncthreads();
    if (tid < 4) {
        int b2 = tid >> 1, c = tid & 1;
        float s = red[(b2 * 4 + 0) * 2 + c] + red[(b2 * 4 + 1) * 2 + c] +
                  red[(b2 * 4 + 2) * 2 + c] + red[(b2 * 4 + 3) * 2 + c];
        out[(blockIdx.x * 2 + b2) * 2 + c] = s + fcb[c];
    }
}

// ------------------------------------------------------------------
extern "C" void kernel_launch(void* const* d_in, const int* in_sizes, int n_in,
                              void* d_out, int out_size) {
    const float* x        = (const float*)d_in[0];
    const float* adj      = (const float*)d_in[1];
    const float* adj_bias = (const float*)d_in[2];
    const float* w1       = (const float*)d_in[3];
    const float* b1       = (const float*)d_in[4];
    const float* w2       = (const float*)d_in[5];
    const float* b2       = (const float*)d_in[6];
    const float* fc_w     = (const float*)d_in[7];
    const float* fc_b     = (const float*)d_in[8];
    float* out = (float*)d_out;

    const int B = in_sizes[0] / (NNODE * CIN);

    cudaFuncSetAttribute(dgcnn_mma_kernel,
                         cudaFuncAttributeMaxDynamicSharedMemorySize,
                         SMEM_TOTAL);

    precompute_kernel<<<1, 1024>>>(adj, adj_bias, w1, b1, w2, b2);
    dgcnn_mma_kernel<<<B / 2, 256, SMEM_TOTAL>>>(x, fc_w, fc_b, out);
}

// round 11
// speedup vs baseline: 8.3990x; 1.2148x over previous
#include <cuda_runtime.h>
#include <cuda_fp16.h>
#include <cstdint>

#define NNODE 32
#define CIN   60
#define HID   128
#define KCH   5

// ---- fragment-order packed weights (one LDG.128 per lane per 16x16 tile) ----
__device__ __align__(16) uint32_t g_W1fh[4][8][4][32][4];
__device__ __align__(16) uint32_t g_W2fh[4][8][8][32][4];
__device__ uint32_t g_Ap[4][32][32];   // chebyshev matrices, packed hi|lo
__device__ float    g_B1[128];
__device__ float    g_B2[128];

__device__ __forceinline__ uint32_t packhl(float v) {
    __half h = __float2half_rn(v);
    __half l = __float2half_rn(v - __half2float(h));
    return (uint32_t)__half_as_ushort(h) | ((uint32_t)__half_as_ushort(l) << 16);
}
__device__ __forceinline__ uint32_t pack_hh(__half a, __half b) {
    return (uint32_t)__half_as_ushort(a) | ((uint32_t)__half_as_ushort(b) << 16);
}

// ------------------------------------------------------------------
__global__ void precompute_kernel(const float* __restrict__ adj,
                                  const float* __restrict__ adj_bias,
                                  const float* __restrict__ w1,
                                  const float* __restrict__ b1,
                                  const float* __restrict__ w2,
                                  const float* __restrict__ b2) {
    __shared__ float a[NNODE][NNODE];
    __shared__ float L[NNODE][NNODE];
    __shared__ float A3[NNODE][NNODE];
    __shared__ float dre[NNODE];

    int tid = threadIdx.x;
    int n = tid >> 5, m = tid & 31;

    float bias = adj_bias[0];
    a[n][m] = fmaxf(adj[n * NNODE + m] + bias, 0.0f);
    __syncthreads();
    if (m == 0) {
        float s = 0.0f;
        for (int j = 0; j < NNODE; j++) s += a[n][j];
        dre[n] = 1.0f / sqrtf(s + 1e-5f);
    }
    __syncthreads();
    L[n][m] = (n == m ? 1.0f : 0.0f) - dre[n] * a[n][m] * dre[m];
    __syncthreads();
    float s = 0.0f;
    for (int j = 0; j < NNODE; j++) s += L[n][j] * L[j][m];
    A3[n][m] = 2.0f * s - (n == m ? 1.0f : 0.0f);
    __syncthreads();
    float s2 = 0.0f;
    for (int j = 0; j < NNODE; j++) s2 += L[n][j] * A3[j][m];
    float a4 = 2.0f * s2 - L[n][m];

    g_Ap[0][n][m] = packhl(n == m ? 1.0f : 0.0f);
    g_Ap[1][n][m] = packhl(L[n][m]);
    g_Ap[2][n][m] = packhl(A3[n][m]);
    g_Ap[3][n][m] = packhl(a4);

    // W1 fragments hi: row=o, col=c (zero pad c>=60)
    for (int idx = tid; idx < 4 * 8 * 4 * 32; idx += blockDim.x) {
        int lane = idx & 31;
        int ct = (idx >> 5) & 3;
        int ot = (idx >> 7) & 7;
        int k = idx >> 10;
        int r0 = lane >> 2, cp = (lane & 3) * 2;
        for (int ai = 0; ai < 4; ai++) {
            int row = ot * 16 + r0 + (ai & 1) * 8;
            int col = ct * 16 + cp + (ai >> 1) * 8;
            float v0 = (col < CIN) ? w1[(col * KCH + k + 1) * HID + row] : 0.0f;
            float v1 = (col + 1 < CIN) ? w1[((col + 1) * KCH + k + 1) * HID + row] : 0.0f;
            g_W1fh[k][ot][ct][lane][ai] =
                pack_hh(__float2half_rn(v0), __float2half_rn(v1));
        }
    }
    // W2 fragments hi only: row=o2, col=o
    for (int idx = tid; idx < 4 * 8 * 8 * 32; idx += blockDim.x) {
        int lane = idx & 31;
        int ct = (idx >> 5) & 7;
        int ot = (idx >> 8) & 7;
        int k = idx >> 11;
        int r0 = lane >> 2, cp = (lane & 3) * 2;
        for (int ai = 0; ai < 4; ai++) {
            int row = ot * 16 + r0 + (ai & 1) * 8;
            int col = ct * 16 + cp + (ai >> 1) * 8;
            float v0 = w2[(col * KCH + k + 1) * HID + row];
            float v1 = w2[((col + 1) * KCH + k + 1) * HID + row];
            g_W2fh[k][ot][ct][lane][ai] =
                pack_hh(__float2half_rn(v0), __float2half_rn(v1));
        }
    }
    if (tid < HID) {
        float s1 = b1[tid];
        for (int c = 0; c < CIN; c++) s1 += w1[(c * KCH) * HID + tid];
        g_B1[tid] = s1;
        float sb = b2[tid];
        for (int c = 0; c < HID; c++) sb += w2[(c * KCH) * HID + tid];
        g_B2[tid] = sb;
    }
}

// ------------------------------------------------------------------
__device__ __forceinline__ uint32_t smem_u32(const void* p) {
    uint32_t a;
    asm("{ .reg .u64 t; cvta.to.shared.u64 t, %1; cvt.u32.u64 %0, t; }"
        : "=r"(a) : "l"(p));
    return a;
}
__device__ __forceinline__ void ldsm4(uint32_t* r, uint32_t addr) {
    asm volatile("ldmatrix.sync.aligned.m8n8.x4.shared.b16 {%0,%1,%2,%3}, [%4];\n"
                 : "=r"(r[0]), "=r"(r[1]), "=r"(r[2]), "=r"(r[3]) : "r"(addr));
}
__device__ __forceinline__ void mma16816(float* d, const uint32_t* a,
                                         uint32_t b0, uint32_t b1) {
    asm volatile(
        "mma.sync.aligned.m16n8k16.row.col.f32.f16.f16.f32 "
        "{%0,%1,%2,%3},{%4,%5,%6,%7},{%8,%9},{%0,%1,%2,%3};\n"
        : "+f"(d[0]), "+f"(d[1]), "+f"(d[2]), "+f"(d[3])
        : "r"(a[0]), "r"(a[1]), "r"(a[2]), "r"(a[3]), "r"(b0), "r"(b1));
}
__device__ __forceinline__ uint32_t pack2(float x, float y) {
    __half2 h = __float22half2_rn(make_float2(x, y));
    return *(uint32_t*)&h;
}

// ---- smem strides (halfs) ----
#define STX 72    // layer1 X rows: [hi 0..63 | pad]
#define STH 136   // layer2 H rows: [hi 0..127 | pad]
#define STA 72    // A: [n][Ah 0..31 | Al 32..63 | pad] (Al kept but unused)

// ---- smem regions (bytes) ----
#define OFF_R1  0        // [64][STH]  X (l1, stride STX) / H (l2, stride STH)
#define OFF_A   17408    // [4][32][STA]                 18432
#define OFF_B1  35840
#define OFF_B2  36352
#define OFF_FC  36864    // [2][128][34] f32             34816
#define OFF_RED 71680
#define SMEM_TOTAL 71808

// A-apply, register-chained, 1-pass: acc += Zh x Ah
__device__ __forceinline__ void apply_chain(float (&acc)[2][4][4],
                                            const float (&d)[2][4][4],
                                            uint32_t sAk, int lane) {
    const uint32_t lrow = (uint32_t)(lane & 15);
    const uint32_t lcol = (uint32_t)((lane >> 4) << 3);
    uint32_t zh2[2][4][2];
#pragma unroll
    for (int t = 0; t < 2; t++)
#pragma unroll
        for (int j = 0; j < 4; j++)
#pragma unroll
            for (int pr = 0; pr < 2; pr++)
                zh2[t][j][pr] = pack2(d[t][j][pr * 2 + 0], d[t][j][pr * 2 + 1]);
#pragma unroll
    for (int kh = 0; kh < 2; kh++) {
        uint32_t BH[2][4];
#pragma unroll
        for (int np = 0; np < 2; np++)
            ldsm4(BH[np], sAk + ((np * 16 + lrow) * STA + kh * 16 + lcol) * 2);
#pragma unroll
        for (int t = 0; t < 2; t++) {
            uint32_t Ah_[4] = {zh2[t][2 * kh][0], zh2[t][2 * kh][1],
                               zh2[t][2 * kh + 1][0], zh2[t][2 * kh + 1][1]};
#pragma unroll
            for (int np = 0; np < 2; np++) {
                mma16816(acc[t][np * 2 + 0], Ah_, BH[np][0], BH[np][2]);
                mma16816(acc[t][np * 2 + 1], Ah_, BH[np][1], BH[np][3]);
            }
        }
    }
}

// ------------------------------------------------------------------
__global__ __launch_bounds__(256, 2) void dgcnn_mma_kernel(
    const float* __restrict__ x,
    const float* __restrict__ fcw,
    const float* __restrict__ fcb,
    float* __restrict__ out) {

    extern __shared__ char smem[];
    __half* S = (__half*)smem;
    const uint32_t sb = smem_u32(smem);
    const int tid = threadIdx.x;
    const int w = tid >> 5, lane = tid & 31;
    const int bp = w >> 2, wb = w & 3;       // batch (0..1), o-quarter

    float* sB1 = (float*)(smem + OFF_B1);
    float* sB2 = (float*)(smem + OFF_B2);
    float* sFC = (float*)(smem + OFF_FC);
    float* red = (float*)(smem + OFF_RED);

    // ---- prologue ----
    for (int i = tid; i < 64 * STH / 2; i += 256) ((uint32_t*)smem)[i] = 0;
    __syncthreads();
    {
        // X hi-only staging
        const float* xb = x + (size_t)blockIdx.x * 64 * CIN;
        for (int i = tid; i < 64 * 15; i += 256) {
            int row = i / 15, c4 = (i - row * 15) * 4;
            float4 v = *(const float4*)&xb[row * CIN + c4];
            uint2 hi;
            hi.x = pack_hh(__float2half_rn(v.x), __float2half_rn(v.y));
            hi.y = pack_hh(__float2half_rn(v.z), __float2half_rn(v.w));
            *(uint2*)&S[row * STX + c4] = hi;
        }
        for (int i = tid; i < 4096; i += 256) {
            int k = i >> 10, n = (i >> 5) & 31, m = i & 31;
            uint32_t u = g_Ap[k][n][m];
            __half2 p = *(__half2*)&u;
            int base = OFF_A / 2 + (k * 32 + n) * STA;
            S[base + m] = p.x;
            S[base + 32 + m] = p.y;
        }
        for (int i = tid; i < 8192; i += 256) {
            int cc = i >> 12, r = i & 4095;
            int n = r >> 7, o2 = r & 127;
            sFC[(cc * 128 + o2) * 34 + n] = fcw[i];
        }
        if (tid < 128) { sB1[tid] = g_B1[tid]; sB2[tid] = g_B2[tid]; }
    }
    __syncthreads();

    const uint32_t bX = sb + OFF_R1 + (bp * 32) * STX * 2;
    const uint32_t bH = sb + OFF_R1 + (bp * 32) * STH * 2;
    const uint32_t lrow = (uint32_t)(lane & 15);
    const uint32_t lcol = (uint32_t)((lane >> 4) << 3);

    float acc[2][4][4];
#pragma unroll
    for (int t = 0; t < 2; t++)
#pragma unroll
        for (int j = 0; j < 4; j++)
#pragma unroll
            for (int e = 0; e < 4; e++) acc[t][j][e] = 0.0f;

    // ================= layer 1 (hi-only) =================
    for (int k = 0; k < 4; k++) {
        float d[2][4][4];
#pragma unroll
        for (int t = 0; t < 2; t++)
#pragma unroll
            for (int j = 0; j < 4; j++)
#pragma unroll
                for (int e = 0; e < 4; e++) d[t][j][e] = 0.0f;

#pragma unroll
        for (int c = 0; c < 4; c++) {
            uint4 ah0 = *(const uint4*)g_W1fh[k][wb * 2 + 0][c][lane];
            uint4 ah1 = *(const uint4*)g_W1fh[k][wb * 2 + 1][c][lane];
            uint32_t Ah0[4] = {ah0.x, ah0.y, ah0.z, ah0.w};
            uint32_t Ah1[4] = {ah1.x, ah1.y, ah1.z, ah1.w};
            uint32_t Bh[2][4];
#pragma unroll
            for (int np = 0; np < 2; np++)
                ldsm4(Bh[np], bX + ((np * 16 + lrow) * STX + c * 16 + lcol) * 2);
#pragma unroll
            for (int np = 0; np < 2; np++) {
                mma16816(d[0][np * 2 + 0], Ah0, Bh[np][0], Bh[np][2]);
                mma16816(d[0][np * 2 + 1], Ah0, Bh[np][1], Bh[np][3]);
                mma16816(d[1][np * 2 + 0], Ah1, Bh[np][0], Bh[np][2]);
                mma16816(d[1][np * 2 + 1], Ah1, Bh[np][1], Bh[np][3]);
            }
        }
        if (k == 0) {
#pragma unroll
            for (int t = 0; t < 2; t++)
#pragma unroll
                for (int j = 0; j < 4; j++)
#pragma unroll
                    for (int e = 0; e < 4; e++) acc[t][j][e] += d[t][j][e];
        } else {
            apply_chain(acc, d, sb + OFF_A + k * 32 * STA * 2, lane);
        }
    }

    // H1 = relu(acc + b1) -> R1 hi-only [row][o], stride STH
    __syncthreads();
#pragma unroll
    for (int t = 0; t < 2; t++)
#pragma unroll
        for (int j = 0; j < 4; j++)
#pragma unroll
            for (int e = 0; e < 4; e++) {
                int o = wb * 32 + t * 16 + (lane >> 2) + ((e >> 1) << 3);
                int n = j * 8 + ((lane & 3) << 1) + (e & 1);
                float v = fmaxf(acc[t][j][e] + sB1[o], 0.0f);
                S[(bp * 32 + n) * STH + o] = __float2half_rn(v);
            }
#pragma unroll
    for (int t = 0; t < 2; t++)
#pragma unroll
        for (int j = 0; j < 4; j++)
#pragma unroll
            for (int e = 0; e < 4; e++) acc[t][j][e] = 0.0f;
    __syncthreads();

    // ================= layer 2 (hi-only) =================
    for (int k2 = 0; k2 < 4; k2++) {
        float d[2][4][4];
#pragma unroll
        for (int t = 0; t < 2; t++)
#pragma unroll
            for (int j = 0; j < 4; j++)
#pragma unroll
                for (int e = 0; e < 4; e++) d[t][j][e] = 0.0f;

#pragma unroll
        for (int c = 0; c < 8; c++) {
            uint4 ah0 = *(const uint4*)g_W2fh[k2][wb * 2 + 0][c][lane];
            uint4 ah1 = *(const uint4*)g_W2fh[k2][wb * 2 + 1][c][lane];
            uint32_t Ah0[4] = {ah0.x, ah0.y, ah0.z, ah0.w};
            uint32_t Ah1[4] = {ah1.x, ah1.y, ah1.z, ah1.w};
#pragma unroll
            for (int np = 0; np < 2; np++) {
                uint32_t Bf[4];
                ldsm4(Bf, bH + ((np * 16 + lrow) * STH + c * 16 + lcol) * 2);
                mma16816(d[0][np * 2 + 0], Ah0, Bf[0], Bf[2]);
                mma16816(d[0][np * 2 + 1], Ah0, Bf[1], Bf[3]);
                mma16816(d[1][np * 2 + 0], Ah1, Bf[0], Bf[2]);
                mma16816(d[1][np * 2 + 1], Ah1, Bf[1], Bf[3]);
            }
        }
        if (k2 == 0) {
#pragma unroll
            for (int t = 0; t < 2; t++)
#pragma unroll
                for (int j = 0; j < 4; j++)
#pragma unroll
                    for (int e = 0; e < 4; e++) acc[t][j][e] += d[t][j][e];
        } else {
            apply_chain(acc, d, sb + OFF_A + k2 * 32 * STA * 2, lane);
        }
    }

    // ---- FC epilogue ----
    float p0 = 0.0f, p1 = 0.0f;
#pragma unroll
    for (int t = 0; t < 2; t++)
#pragma unroll
        for (int j = 0; j < 4; j++)
#pragma unroll
            for (int e = 0; e < 4; e++) {
                int o2 = wb * 32 + t * 16 + (lane >> 2) + ((e >> 1) << 3);
                int n = j * 8 + ((lane & 3) << 1) + (e & 1);
                float v = fmaxf(acc[t][j][e] + sB2[o2], 0.0f);
                p0 += v * sFC[o2 * 34 + n];
                p1 += v * sFC[(128 + o2) * 34 + n];
            }
#pragma unroll
    for (int off = 16; off > 0; off >>= 1) {
        p0 += __shfl_xor_sync(0xFFFFFFFFu, p0, off);
        p1 += __shfl_xor_sync(0xFFFFFFFFu, p1, off);
    }
    if (lane == 0) { red[w * 2] = p0; red[w * 2 + 1] = p1; }
    __syncthreads();
    if (tid < 4) {
        int b2 = tid >> 1, c = tid & 1;
        float s = red[(b2 * 4 + 0) * 2 + c] + red[(b2 * 4 + 1) * 2 + c] +
                  red[(b2 * 4 + 2) * 2 + c] + red[(b2 * 4 + 3) * 2 + c];
        out[(blockIdx.x * 2 + b2) * 2 + c] = s + fcb[c];
    }
}

// ------------------------------------------------------------------
extern "C" void kernel_launch(void* const* d_in, const int* in_sizes, int n_in,
                              void* d_out, int out_size) {
    const float* x        = (const float*)d_in[0];
    const float* adj      = (const float*)d_in[1];
    const float* adj_bias = (const float*)d_in[2];
    const float* w1       = (const float*)d_in[3];
    const float* b1       = (const float*)d_in[4];
    const float* w2       = (const float*)d_in[5];
    const float* b2       = (const float*)d_in[6];
    const float* fc_w     = (const float*)d_in[7];
    const float* fc_b     = (const float*)d_in[8];
    float* out = (float*)d_out;

    const int B = in_sizes[0] / (NNODE * CIN);

    cudaFuncSetAttribute(dgcnn_mma_kernel,
                         cudaFuncAttributeMaxDynamicSharedMemorySize,
                         SMEM_TOTAL);

    precompute_kernel<<<1, 1024>>>(adj, adj_bias, w1, b1, w2, b2);
    dgcnn_mma_kernel<<<B / 2, 256, SMEM_TOTAL>>>(x, fc_w, fc_b, out);
}

// round 12
// speedup vs baseline: 10.4130x; 1.2398x over previous
#include <cuda_runtime.h>
#include <cuda_fp16.h>
#include <cstdint>

#define NNODE 32
#define CIN   60
#define HID   128
#define KCH   5

// ---- fragment-order packed constants (all L2-resident, loaded direct) ----
__device__ __align__(16) uint32_t g_W1fh[4][8][4][32][4];  // A-op frag, layer1
__device__ __align__(16) uint32_t g_W2fh[4][8][8][32][4];  // A-op frag, layer2
__device__ __align__(16) uint32_t g_Af[4][2][2][32][4];    // B-op frag, chebyshev
__device__ __align__(16) float    g_FCf[2][4][2][4][32][4];// FC frag order
__device__ float g_B1[128];
__device__ float g_B2[128];

__device__ __forceinline__ uint32_t pack_hh(__half a, __half b) {
    return (uint32_t)__half_as_ushort(a) | ((uint32_t)__half_as_ushort(b) << 16);
}

// ------------------------------------------------------------------
__global__ void precompute_kernel(const float* __restrict__ adj,
                                  const float* __restrict__ adj_bias,
                                  const float* __restrict__ w1,
                                  const float* __restrict__ b1,
                                  const float* __restrict__ w2,
                                  const float* __restrict__ b2,
                                  const float* __restrict__ fc_w) {
    __shared__ float a[NNODE][NNODE];
    __shared__ float L[NNODE][NNODE];
    __shared__ float A3[NNODE][NNODE];
    __shared__ float A4[NNODE][NNODE];
    __shared__ float dre[NNODE];

    int tid = threadIdx.x;
    int n = tid >> 5, m = tid & 31;

    float bias = adj_bias[0];
    a[n][m] = fmaxf(adj[n * NNODE + m] + bias, 0.0f);
    __syncthreads();
    if (m == 0) {
        float s = 0.0f;
        for (int j = 0; j < NNODE; j++) s += a[n][j];
        dre[n] = 1.0f / sqrtf(s + 1e-5f);
    }
    __syncthreads();
    L[n][m] = (n == m ? 1.0f : 0.0f) - dre[n] * a[n][m] * dre[m];
    __syncthreads();
    float s = 0.0f;
    for (int j = 0; j < NNODE; j++) s += L[n][j] * L[j][m];
    A3[n][m] = 2.0f * s - (n == m ? 1.0f : 0.0f);
    __syncthreads();
    float s2 = 0.0f;
    for (int j = 0; j < NNODE; j++) s2 += L[n][j] * A3[j][m];
    A4[n][m] = 2.0f * s2 - L[n][m];
    __syncthreads();

    // Chebyshev B-operand fragments, hi halves (ldsm.m8n8.x4 emulation)
    for (int idx = tid; idx < 4 * 2 * 2 * 32; idx += blockDim.x) {
        int lane = idx & 31;
        int np = (idx >> 5) & 1;
        int kh = (idx >> 6) & 1;
        int k = idx >> 7;
        for (int q = 0; q < 4; q++) {
            int rn = np * 16 + (q & 1) * 8 + (lane >> 2);
            int cm = kh * 16 + (q >> 1) * 8 + 2 * (lane & 3);
            float v0, v1;
            if (k == 0)      { v0 = (rn == cm) ? 1.0f : 0.0f; v1 = (rn == cm + 1) ? 1.0f : 0.0f; }
            else if (k == 1) { v0 = L[rn][cm];  v1 = L[rn][cm + 1]; }
            else if (k == 2) { v0 = A3[rn][cm]; v1 = A3[rn][cm + 1]; }
            else             { v0 = A4[rn][cm]; v1 = A4[rn][cm + 1]; }
            g_Af[k][kh][np][lane][q] =
                pack_hh(__float2half_rn(v0), __float2half_rn(v1));
        }
    }

    // W1 fragments hi: row=o, col=c (zero pad c>=60)
    for (int idx = tid; idx < 4 * 8 * 4 * 32; idx += blockDim.x) {
        int lane = idx & 31;
        int ct = (idx >> 5) & 3;
        int ot = (idx >> 7) & 7;
        int k = idx >> 10;
        int r0 = lane >> 2, cp = (lane & 3) * 2;
        for (int ai = 0; ai < 4; ai++) {
            int row = ot * 16 + r0 + (ai & 1) * 8;
            int col = ct * 16 + cp + (ai >> 1) * 8;
            float v0 = (col < CIN) ? w1[(col * KCH + k + 1) * HID + row] : 0.0f;
            float v1 = (col + 1 < CIN) ? w1[((col + 1) * KCH + k + 1) * HID + row] : 0.0f;
            g_W1fh[k][ot][ct][lane][ai] =
                pack_hh(__float2half_rn(v0), __float2half_rn(v1));
        }
    }
    // W2 fragments hi: row=o2, col=o
    for (int idx = tid; idx < 4 * 8 * 8 * 32; idx += blockDim.x) {
        int lane = idx & 31;
        int ct = (idx >> 5) & 7;
        int ot = (idx >> 8) & 7;
        int k = idx >> 11;
        int r0 = lane >> 2, cp = (lane & 3) * 2;
        for (int ai = 0; ai < 4; ai++) {
            int row = ot * 16 + r0 + (ai & 1) * 8;
            int col = ct * 16 + cp + (ai >> 1) * 8;
            float v0 = w2[(col * KCH + k + 1) * HID + row];
            float v1 = w2[((col + 1) * KCH + k + 1) * HID + row];
            g_W2fh[k][ot][ct][lane][ai] =
                pack_hh(__float2half_rn(v0), __float2half_rn(v1));
        }
    }
    // FC weights in epilogue fragment order
    for (int idx = tid; idx < 8192; idx += blockDim.x) {
        int e = idx & 3;
        int lane = (idx >> 2) & 31;
        int j = (idx >> 7) & 3;
        int t = (idx >> 9) & 1;
        int wb = (idx >> 10) & 3;
        int cls = idx >> 12;
        int o2 = wb * 32 + t * 16 + (lane >> 2) + ((e >> 1) << 3);
        int nn = j * 8 + ((lane & 3) << 1) + (e & 1);
        g_FCf[cls][wb][t][j][lane][e] = fc_w[cls * 4096 + nn * HID + o2];
    }
    if (tid < HID) {
        float s1 = b1[tid];
        for (int c = 0; c < CIN; c++) s1 += w1[(c * KCH) * HID + tid];
        g_B1[tid] = s1;
        float sb = b2[tid];
        for (int c = 0; c < HID; c++) sb += w2[(c * KCH) * HID + tid];
        g_B2[tid] = sb;
    }
}

// ------------------------------------------------------------------
__device__ __forceinline__ uint32_t smem_u32(const void* p) {
    uint32_t a;
    asm("{ .reg .u64 t; cvta.to.shared.u64 t, %1; cvt.u32.u64 %0, t; }"
        : "=r"(a) : "l"(p));
    return a;
}
__device__ __forceinline__ void ldsm4(uint32_t* r, uint32_t addr) {
    asm volatile("ldmatrix.sync.aligned.m8n8.x4.shared.b16 {%0,%1,%2,%3}, [%4];\n"
                 : "=r"(r[0]), "=r"(r[1]), "=r"(r[2]), "=r"(r[3]) : "r"(addr));
}
__device__ __forceinline__ void mma16816(float* d, const uint32_t* a,
                                         uint32_t b0, uint32_t b1) {
    asm volatile(
        "mma.sync.aligned.m16n8k16.row.col.f32.f16.f16.f32 "
        "{%0,%1,%2,%3},{%4,%5,%6,%7},{%8,%9},{%0,%1,%2,%3};\n"
        : "+f"(d[0]), "+f"(d[1]), "+f"(d[2]), "+f"(d[3])
        : "r"(a[0]), "r"(a[1]), "r"(a[2]), "r"(a[3]), "r"(b0), "r"(b1));
}
__device__ __forceinline__ uint32_t pack2(float x, float y) {
    __half2 h = __float22half2_rn(make_float2(x, y));
    return *(uint32_t*)&h;
}

// ---- smem strides (halfs) ----
#define STX 72    // layer1 X rows: [hi 0..63 | pad]
#define STH 136   // layer2 H rows: [hi 0..127 | pad]

// ---- smem regions (bytes) ----
#define OFF_R1  0        // [64][STH]  X (l1, stride STX) / H (l2, stride STH)
#define OFF_B1  17408
#define OFF_B2  17920
#define OFF_RED 18432
#define SMEM_TOTAL 18560

// A-apply, register-chained, 1-pass: acc += Zh x Ah (Ah direct from gmem frags)
__device__ __forceinline__ void apply_chain(float (&acc)[2][4][4],
                                            const float (&d)[2][4][4],
                                            int k, int lane) {
    uint32_t zh2[2][4][2];
#pragma unroll
    for (int t = 0; t < 2; t++)
#pragma unroll
        for (int j = 0; j < 4; j++)
#pragma unroll
            for (int pr = 0; pr < 2; pr++)
                zh2[t][j][pr] = pack2(d[t][j][pr * 2 + 0], d[t][j][pr * 2 + 1]);
#pragma unroll
    for (int kh = 0; kh < 2; kh++) {
        uint4 b0 = *(const uint4*)g_Af[k][kh][0][lane];
        uint4 b1 = *(const uint4*)g_Af[k][kh][1][lane];
#pragma unroll
        for (int t = 0; t < 2; t++) {
            uint32_t Ah_[4] = {zh2[t][2 * kh][0], zh2[t][2 * kh][1],
                               zh2[t][2 * kh + 1][0], zh2[t][2 * kh + 1][1]};
            mma16816(acc[t][0], Ah_, b0.x, b0.z);
            mma16816(acc[t][1], Ah_, b0.y, b0.w);
            mma16816(acc[t][2], Ah_, b1.x, b1.z);
            mma16816(acc[t][3], Ah_, b1.y, b1.w);
        }
    }
}

// ------------------------------------------------------------------
__global__ __launch_bounds__(256, 2) void dgcnn_mma_kernel(
    const float* __restrict__ x,
    const float* __restrict__ fcb,
    float* __restrict__ out) {

    extern __shared__ char smem[];
    __half* S = (__half*)smem;
    const uint32_t sb = smem_u32(smem);
    const int tid = threadIdx.x;
    const int w = tid >> 5, lane = tid & 31;
    const int bp = w >> 2, wb = w & 3;       // batch (0..1), o-quarter

    float* sB1 = (float*)(smem + OFF_B1);
    float* sB2 = (float*)(smem + OFF_B2);
    float* red = (float*)(smem + OFF_RED);

    // ---- prologue ----
    for (int i = tid; i < 64 * STH / 2; i += 256) ((uint32_t*)smem)[i] = 0;
    __syncthreads();
    {
        const float* xb = x + (size_t)blockIdx.x * 64 * CIN;
        for (int i = tid; i < 64 * 15; i += 256) {
            int row = i / 15, c4 = (i - row * 15) * 4;
            float4 v = *(const float4*)&xb[row * CIN + c4];
            uint2 hi;
            hi.x = pack_hh(__float2half_rn(v.x), __float2half_rn(v.y));
            hi.y = pack_hh(__float2half_rn(v.z), __float2half_rn(v.w));
            *(uint2*)&S[row * STX + c4] = hi;
        }
        if (tid < 128) { sB1[tid] = g_B1[tid]; sB2[tid] = g_B2[tid]; }
    }
    __syncthreads();

    const uint32_t bX = sb + OFF_R1 + (bp * 32) * STX * 2;
    const uint32_t bH = sb + OFF_R1 + (bp * 32) * STH * 2;
    const uint32_t lrow = (uint32_t)(lane & 15);
    const uint32_t lcol = (uint32_t)((lane >> 4) << 3);

    float acc[2][4][4];
#pragma unroll
    for (int t = 0; t < 2; t++)
#pragma unroll
        for (int j = 0; j < 4; j++)
#pragma unroll
            for (int e = 0; e < 4; e++) acc[t][j][e] = 0.0f;

    // ================= layer 1 (hi-only) =================
    for (int k = 0; k < 4; k++) {
        float d[2][4][4];
#pragma unroll
        for (int t = 0; t < 2; t++)
#pragma unroll
            for (int j = 0; j < 4; j++)
#pragma unroll
                for (int e = 0; e < 4; e++) d[t][j][e] = 0.0f;

#pragma unroll
        for (int c = 0; c < 4; c++) {
            uint4 ah0 = *(const uint4*)g_W1fh[k][wb * 2 + 0][c][lane];
            uint4 ah1 = *(const uint4*)g_W1fh[k][wb * 2 + 1][c][lane];
            uint32_t Ah0[4] = {ah0.x, ah0.y, ah0.z, ah0.w};
            uint32_t Ah1[4] = {ah1.x, ah1.y, ah1.z, ah1.w};
            uint32_t Bh[2][4];
#pragma unroll
            for (int np = 0; np < 2; np++)
                ldsm4(Bh[np], bX + ((np * 16 + lrow) * STX + c * 16 + lcol) * 2);
#pragma unroll
            for (int np = 0; np < 2; np++) {
                mma16816(d[0][np * 2 + 0], Ah0, Bh[np][0], Bh[np][2]);
                mma16816(d[0][np * 2 + 1], Ah0, Bh[np][1], Bh[np][3]);
                mma16816(d[1][np * 2 + 0], Ah1, Bh[np][0], Bh[np][2]);
                mma16816(d[1][np * 2 + 1], Ah1, Bh[np][1], Bh[np][3]);
            }
        }
        if (k == 0) {
#pragma unroll
            for (int t = 0; t < 2; t++)
#pragma unroll
                for (int j = 0; j < 4; j++)
#pragma unroll
                    for (int e = 0; e < 4; e++) acc[t][j][e] += d[t][j][e];
        } else {
            apply_chain(acc, d, k, lane);
        }
    }

    // H1 = relu(acc + b1) -> R1 hi-only [row][o], stride STH
    __syncthreads();
#pragma unroll
    for (int t = 0; t < 2; t++)
#pragma unroll
        for (int j = 0; j < 4; j++)
#pragma unroll
            for (int e = 0; e < 4; e++) {
                int o = wb * 32 + t * 16 + (lane >> 2) + ((e >> 1) << 3);
                int n = j * 8 + ((lane & 3) << 1) + (e & 1);
                float v = fmaxf(acc[t][j][e] + sB1[o], 0.0f);
                S[(bp * 32 + n) * STH + o] = __float2half_rn(v);
            }
#pragma unroll
    for (int t = 0; t < 2; t++)
#pragma unroll
        for (int j = 0; j < 4; j++)
#pragma unroll
            for (int e = 0; e < 4; e++) acc[t][j][e] = 0.0f;
    __syncthreads();

    // ================= layer 2 (hi-only) =================
    for (int k2 = 0; k2 < 4; k2++) {
        float d[2][4][4];
#pragma unroll
        for (int t = 0; t < 2; t++)
#pragma unroll
            for (int j = 0; j < 4; j++)
#pragma unroll
                for (int e = 0; e < 4; e++) d[t][j][e] = 0.0f;

#pragma unroll
        for (int c = 0; c < 8; c++) {
            uint4 ah0 = *(const uint4*)g_W2fh[k2][wb * 2 + 0][c][lane];
            uint4 ah1 = *(const uint4*)g_W2fh[k2][wb * 2 + 1][c][lane];
            uint32_t Ah0[4] = {ah0.x, ah0.y, ah0.z, ah0.w};
            uint32_t Ah1[4] = {ah1.x, ah1.y, ah1.z, ah1.w};
#pragma unroll
            for (int np = 0; np < 2; np++) {
                uint32_t Bf[4];
                ldsm4(Bf, bH + ((np * 16 + lrow) * STH + c * 16 + lcol) * 2);
                mma16816(d[0][np * 2 + 0], Ah0, Bf[0], Bf[2]);
                mma16816(d[0][np * 2 + 1], Ah0, Bf[1], Bf[3]);
                mma16816(d[1][np * 2 + 0], Ah1, Bf[0], Bf[2]);
                mma16816(d[1][np * 2 + 1], Ah1, Bf[1], Bf[3]);
            }
        }
        if (k2 == 0) {
#pragma unroll
            for (int t = 0; t < 2; t++)
#pragma unroll
                for (int j = 0; j < 4; j++)
#pragma unroll
                    for (int e = 0; e < 4; e++) acc[t][j][e] += d[t][j][e];
        } else {
            apply_chain(acc, d, k2, lane);
        }
    }

    // ---- FC epilogue (coalesced fragment LDG, no smem) ----
    float p0 = 0.0f, p1 = 0.0f;
#pragma unroll
    for (int t = 0; t < 2; t++)
#pragma unroll
        for (int j = 0; j < 4; j++) {
            float4 f0 = *(const float4*)g_FCf[0][wb][t][j][lane];
            float4 f1 = *(const float4*)g_FCf[1][wb][t][j][lane];
            float v0, v1, v2, v3;
            {
                int ob = wb * 32 + t * 16 + (lane >> 2);
                v0 = fmaxf(acc[t][j][0] + sB2[ob], 0.0f);
                v1 = fmaxf(acc[t][j][1] + sB2[ob], 0.0f);
                v2 = fmaxf(acc[t][j][2] + sB2[ob + 8], 0.0f);
                v3 = fmaxf(acc[t][j][3] + sB2[ob + 8], 0.0f);
            }
            p0 += v0 * f0.x + v1 * f0.y + v2 * f0.z + v3 * f0.w;
            p1 += v0 * f1.x + v1 * f1.y + v2 * f1.z + v3 * f1.w;
        }
#pragma unroll
    for (int off = 16; off > 0; off >>= 1) {
        p0 += __shfl_xor_sync(0xFFFFFFFFu, p0, off);
        p1 += __shfl_xor_sync(0xFFFFFFFFu, p1, off);
    }
    if (lane == 0) { red[w * 2] = p0; red[w * 2 + 1] = p1; }
    __syncthreads();
    if (tid < 4) {
        int b2 = tid >> 1, c = tid & 1;
        float s = red[(b2 * 4 + 0) * 2 + c] + red[(b2 * 4 + 1) * 2 + c] +
                  red[(b2 * 4 + 2) * 2 + c] + red[(b2 * 4 + 3) * 2 + c];
        out[(blockIdx.x * 2 + b2) * 2 + c] = s + fcb[c];
    }
}

// ------------------------------------------------------------------
extern "C" void kernel_launch(void* const* d_in, const int* in_sizes, int n_in,
                              void* d_out, int out_size) {
    const float* x        = (const float*)d_in[0];
    const float* adj      = (const float*)d_in[1];
    const float* adj_bias = (const float*)d_in[2];
    const float* w1       = (const float*)d_in[3];
    const float* b1       = (const float*)d_in[4];
    const float* w2       = (const float*)d_in[5];
    const float* b2       = (const float*)d_in[6];
    const float* fc_w     = (const float*)d_in[7];
    const float* fc_b     = (const float*)d_in[8];
    float* out = (float*)d_out;

    const int B = in_sizes[0] / (NNODE * CIN);

    cudaFuncSetAttribute(dgcnn_mma_kernel,
                         cudaFuncAttributeMaxDynamicSharedMemorySize,
                         SMEM_TOTAL);

    precompute_kernel<<<1, 1024>>>(adj, adj_bias, w1, b1, w2, b2, fc_w);
    dgcnn_mma_kernel<<<B / 2, 256, SMEM_TOTAL>>>(x, fc_b, out);
}